// round 7
// baseline (speedup 1.0000x reference)
#include <cuda_runtime.h>
#include <math.h>

#define H 256
#define S 32
#define NB 4096            // batch
#define BS (NB * S)        // 131072 flattened rows
#define NH 4
#define HD 64
#define BH (NH * NB)       // 16384 (head*batch axis length)

// ------------------------- scratch (__device__ globals) -------------------------
__device__ float g_feat[BS * H];
__device__ float g_q[BS * H];
__device__ float g_k[BS * H];
__device__ float g_v[BS * H];
__device__ float g_vr[BS * H];
__device__ float g_attn[BS * H];
__device__ float g_xa[BS * H];
__device__ float g_xb[BS * H];
__device__ float g_scores[(size_t)BH * S * S];   // [bh][q][k]
__device__ float g_pmax[32 * S * S];
__device__ float g_psum[32 * S * S];
__device__ float g_smax[S * S];
__device__ float g_ssum[S * S];
__device__ float g_rowsum[NB * H];
__device__ float g_gi[(size_t)BS * 3 * H];
__device__ float g_gh[(size_t)BS * 3 * H];

// ------------------------- epilogue activations -------------------------
template <int EPI>
__device__ __forceinline__ float act(float v) {
    if (EPI == 1) return fmaxf(v, 0.f);          // relu
    if (EPI == 2) return tanhf(v);               // tanh
    if (EPI == 3) return v > 0.f ? v : 0.01f * v; // leaky relu
    return v;
}

// ------------------------- tiled SGEMM body (128x128x16, 256 thr) -------------------------
// C[m,n] = act(sum_k A[m,k] * B[k,n] + bias[n])      (TRANSB: B stored [N,K])
template <int EPI, bool TRANSB>
__device__ __forceinline__ void gemm_body(
    const float* __restrict__ A, int lda,
    const float* __restrict__ Bm, int ldb,
    const float* __restrict__ bias,
    float* __restrict__ C, int ldc,
    int K, int m0, int n0)
{
    __shared__ float As[16][128];
    __shared__ float Bs[16][128];
    const int t  = threadIdx.x;
    const int tx = t & 15, ty = t >> 4;

    float acc[8][8];
#pragma unroll
    for (int i = 0; i < 8; i++)
#pragma unroll
        for (int j = 0; j < 8; j++) acc[i][j] = 0.f;

    const int ra = t >> 2;          // 0..63
    const int ca = (t & 3) << 2;    // 0,4,8,12
    const int rb = t >> 5;          // 0..7
    const int cb = (t & 31) << 2;   // 0..124

    for (int k0 = 0; k0 < K; k0 += 16) {
        // A tile: 128 rows x 16 k, stored transposed As[k][row]
        float4 a0 = *(const float4*)(A + (size_t)(m0 + ra) * lda + k0 + ca);
        float4 a1 = *(const float4*)(A + (size_t)(m0 + ra + 64) * lda + k0 + ca);
        As[ca + 0][ra] = a0.x; As[ca + 1][ra] = a0.y;
        As[ca + 2][ra] = a0.z; As[ca + 3][ra] = a0.w;
        As[ca + 0][ra + 64] = a1.x; As[ca + 1][ra + 64] = a1.y;
        As[ca + 2][ra + 64] = a1.z; As[ca + 3][ra + 64] = a1.w;

        if (!TRANSB) {
            float4 b0 = *(const float4*)(Bm + (size_t)(k0 + rb) * ldb + n0 + cb);
            float4 b1 = *(const float4*)(Bm + (size_t)(k0 + rb + 8) * ldb + n0 + cb);
            *(float4*)&Bs[rb][cb]     = b0;
            *(float4*)&Bs[rb + 8][cb] = b1;
        } else {
            float4 b0 = *(const float4*)(Bm + (size_t)(n0 + ra) * ldb + k0 + ca);
            float4 b1 = *(const float4*)(Bm + (size_t)(n0 + ra + 64) * ldb + k0 + ca);
            Bs[ca + 0][ra] = b0.x; Bs[ca + 1][ra] = b0.y;
            Bs[ca + 2][ra] = b0.z; Bs[ca + 3][ra] = b0.w;
            Bs[ca + 0][ra + 64] = b1.x; Bs[ca + 1][ra + 64] = b1.y;
            Bs[ca + 2][ra + 64] = b1.z; Bs[ca + 3][ra + 64] = b1.w;
        }
        __syncthreads();

#pragma unroll
        for (int kk = 0; kk < 16; kk++) {
            float av[8], bv[8];
#pragma unroll
            for (int i = 0; i < 8; i++) av[i] = As[kk][ty * 8 + i];
#pragma unroll
            for (int j = 0; j < 8; j++) bv[j] = Bs[kk][tx * 8 + j];
#pragma unroll
            for (int i = 0; i < 8; i++)
#pragma unroll
                for (int j = 0; j < 8; j++)
                    acc[i][j] = fmaf(av[i], bv[j], acc[i][j]);
        }
        __syncthreads();
    }

#pragma unroll
    for (int i = 0; i < 8; i++) {
        int row = m0 + ty * 8 + i;
#pragma unroll
        for (int j = 0; j < 8; j += 4) {
            int col = n0 + tx * 8 + j;
            float4 v;
            v.x = act<EPI>(acc[i][j + 0] + bias[col + 0]);
            v.y = act<EPI>(acc[i][j + 1] + bias[col + 1]);
            v.z = act<EPI>(acc[i][j + 2] + bias[col + 2]);
            v.w = act<EPI>(acc[i][j + 3] + bias[col + 3]);
            *(float4*)(C + (size_t)row * ldc + col) = v;
        }
    }
}

template <int EPI, bool TRANSB>
__global__ void __launch_bounds__(256) sgemm_k(
    const float* __restrict__ A, int lda,
    const float* __restrict__ Bm, int ldb,
    const float* __restrict__ bias,
    float* __restrict__ C, int ldc, int K)
{
    gemm_body<EPI, TRANSB>(A, lda, Bm, ldb, bias, C, ldc, K,
                           blockIdx.y * 128, blockIdx.x * 128);
}

// per-sender GEMM: C[b,s,:] = X[b,s,:] @ W[s] + bvec[s], s = blockIdx.z
__global__ void __launch_bounds__(256) sender_gemm_k(
    const float* __restrict__ X,
    const float* __restrict__ W,
    const float* __restrict__ bvec,
    float* __restrict__ Cout)
{
    int s = blockIdx.z;
    gemm_body<0, false>(X + s * H, S * H,
                        W + (size_t)s * H * H, H,
                        bvec + s * H,
                        Cout + s * H, S * H,
                        H, blockIdx.y * 128, blockIdx.x * 128);
}

// ------------------------- attention scores -------------------------
// scores[h*NB+b][q][k] = dot_d(Q[b,q,64h+d], K[b,k,64h+d]) / 8
__global__ void __launch_bounds__(256) scores_k(
    const float* __restrict__ Q, const float* __restrict__ Kt)
{
    __shared__ float Ks[32][257];   // stride 257 (odd) -> conflict-free lane-strided reads
    int b = blockIdx.x;
    int t = threadIdx.x;
    for (int idx = t; idx < S * H; idx += 256) {
        int k = idx >> 8, c = idx & 255;
        Ks[k][c] = Kt[(size_t)(b * S + k) * H + c];
    }
    __syncthreads();
    int lane = t & 31, w = t >> 5;
#pragma unroll
    for (int qi = 0; qi < 4; qi++) {
        int q = w + qi * 8;
        const float* qrow = Q + (size_t)(b * S + q) * H;
#pragma unroll
        for (int h = 0; h < NH; h++) {
            float accv = 0.f;
#pragma unroll 16
            for (int d = 0; d < HD; d++)
                accv = fmaf(__ldg(qrow + h * HD + d), Ks[lane][h * HD + d], accv);
            g_scores[(size_t)(h * NB + b) * (S * S) + q * S + lane] = accv * 0.125f;
        }
    }
}

// ------------------------- softmax over axis 0 (length 16384) per (q,k) -------------------------
__global__ void __launch_bounds__(256) smax_part_k()
{
    int chunk = blockIdx.x, q = blockIdx.y;
    int t = threadIdx.x, k = t & 31, g = t >> 5;
    float m = -1e30f, sv = 0.f;
    int base = chunk * 512 + g;
    for (int i = 0; i < 64; i++) {
        int bh = base + i * 8;
        float v = g_scores[(size_t)bh * 1024 + q * 32 + k];
        if (v > m) { sv = sv * expf(m - v) + 1.f; m = v; }
        else       { sv += expf(v - m); }
    }
    __shared__ float sm[8][32], ss[8][32];
    sm[g][k] = m; ss[g][k] = sv;
    __syncthreads();
    if (t < 32) {
        float M = sm[0][k];
#pragma unroll
        for (int j = 1; j < 8; j++) M = fmaxf(M, sm[j][k]);
        float Sv = 0.f;
#pragma unroll
        for (int j = 0; j < 8; j++) Sv += ss[j][k] * expf(sm[j][k] - M);
        g_pmax[chunk * 1024 + q * 32 + k] = M;
        g_psum[chunk * 1024 + q * 32 + k] = Sv;
    }
}

__global__ void smax_final_k()
{
    int t = threadIdx.x;  // 1024 = (q,k) pairs
    float M = -1e30f;
    for (int c = 0; c < 32; c++) M = fmaxf(M, g_pmax[c * 1024 + t]);
    float Sv = 0.f;
    for (int c = 0; c < 32; c++) Sv += g_psum[c * 1024 + t] * expf(g_pmax[c * 1024 + t] - M);
    g_smax[t] = M;
    g_ssum[t] = Sv;
}

// ------------------------- weighted-V + Vr + relu + InstanceNorm (fused) -------------------------
__global__ void __launch_bounds__(256) attnout_k(
    const float* __restrict__ V, const float* __restrict__ Vr,
    const float* __restrict__ gamma, const float* __restrict__ beta,
    float* __restrict__ out)
{
    __shared__ float Vsm[32][256];
    __shared__ float wsm[4][32];
    __shared__ float s_stat[2];
    __shared__ float red[2][8];
    __shared__ float s_smax[1024], s_rs[1024];
    int b = blockIdx.x;
    int t = threadIdx.x;
    for (int idx = t; idx < 32 * 256; idx += 256)
        Vsm[idx >> 8][idx & 255] = V[(size_t)(b * 32) * 256 + idx];
    for (int idx = t; idx < 1024; idx += 256) {
        s_smax[idx] = g_smax[idx];
        s_rs[idx]   = 1.f / g_ssum[idx];
    }
    float gam = gamma[t], bet = beta[t];
    int lane = t & 31, wid = t >> 5;
    int hh = t >> 6;
    __syncthreads();
    for (int q = 0; q < 32; q++) {
        if (t < 128) {
            int h = t >> 5, k = t & 31;
            float svv = g_scores[(size_t)(h * NB + b) * 1024 + q * 32 + k];
            wsm[h][k] = expf(svv - s_smax[q * 32 + k]) * s_rs[q * 32 + k];
        }
        __syncthreads();
        float accv = 0.f;
#pragma unroll 8
        for (int k = 0; k < 32; k++)
            accv = fmaf(wsm[hh][k], Vsm[k][t], accv);
        float o = fmaxf(accv + Vr[(size_t)(b * 32 + q) * 256 + t], 0.f);
        float v1 = o, v2 = o * o;
#pragma unroll
        for (int off = 16; off; off >>= 1) {
            v1 += __shfl_down_sync(0xffffffffu, v1, off);
            v2 += __shfl_down_sync(0xffffffffu, v2, off);
        }
        if (lane == 0) { red[0][wid] = v1; red[1][wid] = v2; }
        __syncthreads();
        if (t == 0) {
            float s1 = 0.f, s2 = 0.f;
#pragma unroll
            for (int i = 0; i < 8; i++) { s1 += red[0][i]; s2 += red[1][i]; }
            float mu  = s1 * (1.f / 256.f);
            float var = s2 * (1.f / 256.f) - mu * mu;
            s_stat[0] = mu;
            s_stat[1] = rsqrtf(var + 1e-5f);
        }
        __syncthreads();
        out[(size_t)(b * 32 + q) * 256 + t] = gam * ((o - s_stat[0]) * s_stat[1]) + bet;
        __syncthreads();
    }
}

// ------------------------- GNN helpers -------------------------
__global__ void rowsum_k(const float* __restrict__ X, float* __restrict__ R)
{
    int idx = blockIdx.x * 256 + threadIdx.x;  // NB*H
    int b = idx >> 8, h = idx & 255;
    float accv = 0.f;
#pragma unroll
    for (int s = 0; s < 32; s++)
        accv += X[(size_t)((b << 5) + s) * 256 + h];
    R[idx] = accv;
}

__global__ void sub_bcast_k(const float* __restrict__ R,
                            const float* __restrict__ S1,
                            float* __restrict__ S2)
{
    size_t idx = (size_t)blockIdx.x * 256 + threadIdx.x;
    int row = (int)(idx >> 8);
    int b = row >> 5;
    int h = (int)(idx & 255);
    S2[idx] = R[(b << 8) + h] - S1[idx];
}

__global__ void gru_k(const float* __restrict__ xin, float* __restrict__ xout)
{
    size_t idx = (size_t)blockIdx.x * 256 + threadIdx.x;
    int row = (int)(idx >> 8), c = (int)(idx & 255);
    size_t base = (size_t)row * 768 + c;
    float ir = g_gi[base], iz = g_gi[base + 256], inn = g_gi[base + 512];
    float hr = g_gh[base], hz = g_gh[base + 256], hn = g_gh[base + 512];
    float r = 1.f / (1.f + expf(-(ir + hr)));
    float z = 1.f / (1.f + expf(-(iz + hz)));
    float n = tanhf(inn + r * hn);
    float x = xin[idx];
    xout[idx] = x + (1.f - z) * n + z * x;   // x + h_new, h = x
}

// ------------------------- final credit head -------------------------
__global__ void __launch_bounds__(256) cred_k(
    const float* __restrict__ M1, const float* __restrict__ M2,
    float* __restrict__ out)
{
    int wid = threadIdx.x >> 5, lane = threadIdx.x & 31;
    int row = blockIdx.x * 8 + wid;
    const float* p1 = M1 + (size_t)row * 256;
    const float* p2 = M2 + (size_t)row * 256;
    float accv = 0.f;
#pragma unroll
    for (int j = 0; j < 8; j++)
        accv = fmaf(p1[lane + j * 32], p2[lane + j * 32], accv);
#pragma unroll
    for (int off = 16; off; off >>= 1)
        accv += __shfl_down_sync(0xffffffffu, accv, off);
    if (lane == 0) out[row] = 1.f / (1.f + expf(-accv));
}

// ------------------------- host orchestration -------------------------
static void gnn_call(const float* x_in, float* x_out,
                     const float* mp_w1, const float* mp_b1,
                     const float* mp_w3, const float* mp_b3,
                     const float* wih, const float* whh,
                     const float* bih, const float* bhh,
                     float* s1, float* s2, float* rowsum,
                     float* gi, float* gh)
{
    dim3 gs(2, 32, 32);  // n-tiles, b-tiles, sender
    sender_gemm_k<<<gs, 256>>>(x_in, mp_w1, mp_b1, s1);
    rowsum_k<<<(NB * H) / 256, 256>>>(s1, rowsum);
    sub_bcast_k<<<(BS * H) / 256, 256>>>(rowsum, s1, s2);
    sender_gemm_k<<<gs, 256>>>(s2, mp_w3, mp_b3, s1);    // s3 reuses s1
    sgemm_k<0, true><<<dim3(6, 1024), 256>>>(s1,   256, wih, 256, bih, gi, 768, 256);
    sgemm_k<0, true><<<dim3(6, 1024), 256>>>(x_in, 256, whh, 256, bhh, gh, 768, 256);
    gru_k<<<(BS * H) / 256, 256>>>(x_in, x_out);
}

extern "C" void kernel_launch(void* const* d_in, const int* in_sizes, int n_in,
                              void* d_out, int out_size)
{
    (void)in_sizes; (void)n_in; (void)out_size;
    const float* inputs  = (const float*)d_in[0];
    const float* embed_w = (const float*)d_in[1];
    const float* embed_b = (const float*)d_in[2];
    const float* wq  = (const float*)d_in[3];
    const float* bq  = (const float*)d_in[4];
    const float* wk  = (const float*)d_in[5];
    const float* bk  = (const float*)d_in[6];
    const float* wv  = (const float*)d_in[7];
    const float* bv  = (const float*)d_in[8];
    const float* wvr = (const float*)d_in[9];
    const float* bvr = (const float*)d_in[10];
    const float* gamma = (const float*)d_in[11];
    const float* beta  = (const float*)d_in[12];
    const float* mp_w1 = (const float*)d_in[13];
    const float* mp_b1 = (const float*)d_in[14];
    const float* mp_w3 = (const float*)d_in[15];
    const float* mp_b3 = (const float*)d_in[16];
    const float* gru_wih = (const float*)d_in[17];
    const float* gru_whh = (const float*)d_in[18];
    const float* gru_bih = (const float*)d_in[19];
    const float* gru_bhh = (const float*)d_in[20];
    const float* mlp1_w = (const float*)d_in[21];
    const float* mlp1_b = (const float*)d_in[22];
    const float* mlp2_w = (const float*)d_in[23];
    const float* mlp2_b = (const float*)d_in[24];

    float *feat, *qb, *kb, *vb, *vrb, *attn, *xa, *xb, *rowsum, *gi, *gh;
    cudaGetSymbolAddress((void**)&feat,   g_feat);
    cudaGetSymbolAddress((void**)&qb,     g_q);
    cudaGetSymbolAddress((void**)&kb,     g_k);
    cudaGetSymbolAddress((void**)&vb,     g_v);
    cudaGetSymbolAddress((void**)&vrb,    g_vr);
    cudaGetSymbolAddress((void**)&attn,   g_attn);
    cudaGetSymbolAddress((void**)&xa,     g_xa);
    cudaGetSymbolAddress((void**)&xb,     g_xb);
    cudaGetSymbolAddress((void**)&rowsum, g_rowsum);
    cudaGetSymbolAddress((void**)&gi,     g_gi);
    cudaGetSymbolAddress((void**)&gh,     g_gh);

    float* out_cred = (float*)d_out;
    float* out_fs   = (float*)d_out + BS;   // fs written in place

    dim3 g2(2, 1024);
    // feat = tanh(inputs @ embed_w + b)
    sgemm_k<2, false><<<g2, 256>>>(inputs, 256, embed_w, 256, embed_b, feat, 256, 256);
    // Q/K/V/Vr = relu(feat @ W + b)
    sgemm_k<1, false><<<g2, 256>>>(feat, 256, wq,  256, bq,  qb,  256, 256);
    sgemm_k<1, false><<<g2, 256>>>(feat, 256, wk,  256, bk,  kb,  256, 256);
    sgemm_k<1, false><<<g2, 256>>>(feat, 256, wv,  256, bv,  vb,  256, 256);
    sgemm_k<1, false><<<g2, 256>>>(feat, 256, wvr, 256, bvr, vrb, 256, 256);
    // attention
    scores_k<<<NB, 256>>>(qb, kb);
    smax_part_k<<<dim3(32, 32), 256>>>();
    smax_final_k<<<1, 1024>>>();
    attnout_k<<<NB, 256>>>(vb, vrb, gamma, beta, attn);
    // GNN x4 (first output = fs, written directly to d_out region)
    gnn_call(attn,   out_fs, mp_w1, mp_b1, mp_w3, mp_b3, gru_wih, gru_whh, gru_bih, gru_bhh, qb, kb, rowsum, gi, gh);
    gnn_call(out_fs, xa,     mp_w1, mp_b1, mp_w3, mp_b3, gru_wih, gru_whh, gru_bih, gru_bhh, qb, kb, rowsum, gi, gh);
    gnn_call(xa,     xb,     mp_w1, mp_b1, mp_w3, mp_b3, gru_wih, gru_whh, gru_bih, gru_bhh, qb, kb, rowsum, gi, gh);
    gnn_call(xb,     xa,     mp_w1, mp_b1, mp_w3, mp_b3, gru_wih, gru_whh, gru_bih, gru_bhh, qb, kb, rowsum, gi, gh);
    // head: m1 = tanh(fs3@mlp1), m2 = leaky(fs3@mlp2), cred = sigmoid(sum(m1*m2))
    sgemm_k<2, false><<<g2, 256>>>(xa, 256, mlp1_w, 256, mlp1_b, qb, 256, 256);
    sgemm_k<3, false><<<g2, 256>>>(xa, 256, mlp2_w, 256, mlp2_b, kb, 256, 256);
    cred_k<<<BS / 8, 256>>>(qb, kb, out_cred);
}

// round 11
// speedup vs baseline: 1.2029x; 1.2029x over previous
#include <cuda_runtime.h>
#include <cstdint>
#include <math.h>

#define H 256
#define S 32
#define NB 4096            // batch
#define BS (NB * S)        // 131072 flattened rows
#define NH 4
#define HD 64
#define BH (NH * NB)       // 16384 (head*batch axis length)

// ------------------------- scratch (__device__ globals) -------------------------
__device__ float g_feat[BS * H];
__device__ float g_q[BS * H];
__device__ float g_k[BS * H];
__device__ float g_v[BS * H];
__device__ float g_vr[BS * H];
__device__ float g_attn[BS * H];
__device__ float g_xa[BS * H];
__device__ float g_xb[BS * H];
__device__ float g_scores[(size_t)BH * S * S];   // [bh][q][k]
__device__ float g_pmax[32 * S * S];
__device__ float g_psum[32 * S * S];
__device__ float g_smax[S * S];
__device__ float g_ssum[S * S];
__device__ float g_rowsum[NB * H];
__device__ float g_gi[(size_t)BS * 3 * H];
__device__ float g_gh[(size_t)BS * 3 * H];
// transposed weights ([N,K] layout for the mma B operand)
__device__ float g_wt7[7 * H * H];        // embed, wq, wk, wv, wvr, mlp1, mlp2
__device__ float g_w1t[S * H * H];
__device__ float g_w3t[S * H * H];

// ------------------------- helpers -------------------------
__device__ __forceinline__ uint32_t f2tf(float f) {
    uint32_t r;
    asm("cvt.rna.tf32.f32 %0, %1;" : "=r"(r) : "f"(f));
    return r;
}
// split x into tf32 hi + tf32 lo (combined ~21 mantissa bits)
__device__ __forceinline__ void split_tf(float x, uint32_t& hi, uint32_t& lo) {
    hi = f2tf(x);
    lo = f2tf(x - __uint_as_float(hi));
}

// D += A@B  (m16n8k8 tf32, row.col)
__device__ __forceinline__ void mma8(float* d, const uint32_t* a, const uint32_t* b) {
    asm volatile("mma.sync.aligned.m16n8k8.row.col.f32.tf32.tf32.f32 "
        "{%0,%1,%2,%3}, {%4,%5,%6,%7}, {%8,%9}, {%0,%1,%2,%3};"
        : "+f"(d[0]), "+f"(d[1]), "+f"(d[2]), "+f"(d[3])
        : "r"(a[0]), "r"(a[1]), "r"(a[2]), "r"(a[3]), "r"(b[0]), "r"(b[1]));
}

// ------------------------- epilogue activations -------------------------
template <int EPI>
__device__ __forceinline__ float act(float v) {
    if (EPI == 1) return fmaxf(v, 0.f);           // relu
    if (EPI == 2) return tanhf(v);                // tanh
    if (EPI == 3) return v > 0.f ? v : 0.01f * v; // leaky relu
    return v;
}

// ------------------------- mma.sync 3xTF32 GEMM -------------------------
// C[z][m0+0..127, n0+0..127] = act( A[z] @ Bt[z]^T + bias[z] )
// A row-major [M, K=256] (lda floats, z-stride az)
// Bt row-major [N, K=256] (ldb = 256, z-stride bz)
//
// smem (dynamic, 128 KB): A[(p*2+comp)*4096], B[16384 + (p*2+comp)*4096] (u32 words)
// comp 0 = tf32 hi, comp 1 = tf32 lo.
// Fragment-major layout with c^ks swizzle (conflict-free STS.32 and LDS.64):
//   A word: ((mt*4+ks)*2 + r8)*64 + g*8 + ((c^ks)<<1) + half
//   B word: (nti*32 + ks*8 + n8)*8 + ((c^ks)<<1) + half
// where for k_local in [0,32): ks=k>>3, half=(k>>2)&1, c=k&3.
template <int EPI>
__global__ void __launch_bounds__(256) mm_k(
    const float* __restrict__ A, long lda, long az,
    const float* __restrict__ B, long bz,
    const float* __restrict__ bias, long biz,
    float* __restrict__ C, long ldc, long cz)
{
    extern __shared__ uint32_t smem[];
    const int t = threadIdx.x;
    const int m0 = blockIdx.y * 128;
    const int n0 = blockIdx.x * 128;
    const int z  = blockIdx.z;
    const float* Ap = A + (size_t)z * az + (size_t)m0 * lda;
    const float* Bp = B + (size_t)z * bz + (size_t)n0 * 256;
    const float* bp = bias + (size_t)z * biz + n0;
    float* Cp = C + (size_t)z * cz + (size_t)m0 * ldc + n0;

    const int lane = t & 31, w = t >> 5;
    const int wM = w >> 2, wN = w & 3;           // warp grid 2(M) x 4(N)
    const int g = lane >> 2, cl = lane & 3;

    float acc[4][4][4];
#pragma unroll
    for (int i = 0; i < 4; i++)
#pragma unroll
        for (int j = 0; j < 4; j++)
#pragma unroll
            for (int k = 0; k < 4; k++) acc[i][j][k] = 0.f;

    float4 va[4], vb[4];

    // ---- staging load (gmem -> regs) for k-chunk base kb ----
    auto ldstage = [&](int kb) {
#pragma unroll
        for (int i = 0; i < 4; i++) {
            int idx = t + i * 256, row = idx >> 3, f4 = idx & 7;
            va[i] = *(const float4*)(Ap + (size_t)row * lda + kb + f4 * 4);
            vb[i] = *(const float4*)(Bp + (size_t)row * 256 + kb + f4 * 4);
        }
    };
    // ---- regs -> smem (hi/lo tf32 split + fragment-major swizzled layout) ----
    auto ststage = [&](int p) {
        uint32_t* dA0 = smem + (p * 2 + 0) * 4096;
        uint32_t* dA1 = smem + (p * 2 + 1) * 4096;
        uint32_t* dB0 = smem + 16384 + (p * 2 + 0) * 4096;
        uint32_t* dB1 = smem + 16384 + (p * 2 + 1) * 4096;
#pragma unroll
        for (int i = 0; i < 4; i++) {
            int idx = t + i * 256, row = idx >> 3, f4 = idx & 7;
            int ks = f4 >> 1, half = f4 & 1;
            uint32_t hx, lx, hy, ly, hz, lz, hw, lw;
            // A
            {
                int mt = row >> 4, r = row & 15, r8 = r >> 3, ga = r & 7;
                int off = (((mt * 4 + ks) * 2 + r8) << 6) + ga * 8 + half;
                split_tf(va[i].x, hx, lx); split_tf(va[i].y, hy, ly);
                split_tf(va[i].z, hz, lz); split_tf(va[i].w, hw, lw);
                uint32_t* d0 = dA0 + off;
                uint32_t* d1 = dA1 + off;
                d0[(0 ^ ks) << 1] = hx; d1[(0 ^ ks) << 1] = lx;
                d0[(1 ^ ks) << 1] = hy; d1[(1 ^ ks) << 1] = ly;
                d0[(2 ^ ks) << 1] = hz; d1[(2 ^ ks) << 1] = lz;
                d0[(3 ^ ks) << 1] = hw; d1[(3 ^ ks) << 1] = lw;
            }
            // B
            {
                int nti = row >> 3, n8 = row & 7;
                int off = (nti * 32 + ks * 8 + n8) * 8 + half;
                split_tf(vb[i].x, hx, lx); split_tf(vb[i].y, hy, ly);
                split_tf(vb[i].z, hz, lz); split_tf(vb[i].w, hw, lw);
                uint32_t* d0 = dB0 + off;
                uint32_t* d1 = dB1 + off;
                d0[(0 ^ ks) << 1] = hx; d1[(0 ^ ks) << 1] = lx;
                d0[(1 ^ ks) << 1] = hy; d1[(1 ^ ks) << 1] = ly;
                d0[(2 ^ ks) << 1] = hz; d1[(2 ^ ks) << 1] = lz;
                d0[(3 ^ ks) << 1] = hw; d1[(3 ^ ks) << 1] = lw;
            }
        }
    };
    // ---- one k32 chunk: 3xTF32 mma ----
    auto compute = [&](int p) {
        const uint32_t* sA0 = smem + (p * 2 + 0) * 4096;
        const uint32_t* sA1 = smem + (p * 2 + 1) * 4096;
        const uint32_t* sB0 = smem + 16384 + (p * 2 + 0) * 4096;
        const uint32_t* sB1 = smem + 16384 + (p * 2 + 1) * 4096;
#pragma unroll
        for (int ks = 0; ks < 4; ks++) {
            const int cx = ((cl ^ ks) << 1);
            uint32_t a0[4][4], a1[4][4], b0[4][2], b1[4][2];
#pragma unroll
            for (int mt = 0; mt < 4; mt++) {
                int mtg = wM * 4 + mt;
                int off = (((mtg * 4 + ks) * 2) << 6) + g * 8 + cx;
                uint2 lo0 = *(const uint2*)(sA0 + off);
                uint2 hi0 = *(const uint2*)(sA0 + off + 64);
                a0[mt][0] = lo0.x; a0[mt][2] = lo0.y;
                a0[mt][1] = hi0.x; a0[mt][3] = hi0.y;
                uint2 lo1 = *(const uint2*)(sA1 + off);
                uint2 hi1 = *(const uint2*)(sA1 + off + 64);
                a1[mt][0] = lo1.x; a1[mt][2] = lo1.y;
                a1[mt][1] = hi1.x; a1[mt][3] = hi1.y;
            }
#pragma unroll
            for (int nt = 0; nt < 4; nt++) {
                int ntg = wN * 4 + nt;
                int off = (ntg * 32 + ks * 8 + g) * 8 + cx;
                uint2 v0 = *(const uint2*)(sB0 + off);
                b0[nt][0] = v0.x; b0[nt][1] = v0.y;
                uint2 v1 = *(const uint2*)(sB1 + off);
                b1[nt][0] = v1.x; b1[nt][1] = v1.y;
            }
#pragma unroll
            for (int mt = 0; mt < 4; mt++)
#pragma unroll
                for (int nt = 0; nt < 4; nt++) {
                    mma8(acc[mt][nt], a0[mt], b0[nt]);   // hi*hi
                    mma8(acc[mt][nt], a0[mt], b1[nt]);   // hi*lo
                    mma8(acc[mt][nt], a1[mt], b0[nt]);   // lo*hi
                }
        }
    };

    // ---- mainloop: 8 chunks, double buffered ----
    ldstage(0);
    ststage(0);
    __syncthreads();
    int p = 0;
    for (int ch = 0; ch < 8; ch++) {
        if (ch < 7) ldstage((ch + 1) * 32);
        compute(p);
        if (ch < 7) {
            ststage(p ^ 1);
            __syncthreads();
            p ^= 1;
        }
    }

    // ---- epilogue: bias + act, float2 stores ----
    const int wm = wM * 64, wn = wN * 32;
#pragma unroll
    for (int mt = 0; mt < 4; mt++) {
        int r0 = wm + mt * 16 + g;
#pragma unroll
        for (int nt = 0; nt < 4; nt++) {
            int col = wn + nt * 8 + (cl << 1);
            float2 b2 = *(const float2*)(bp + col);
            float2 o0, o1;
            o0.x = act<EPI>(acc[mt][nt][0] + b2.x);
            o0.y = act<EPI>(acc[mt][nt][1] + b2.y);
            o1.x = act<EPI>(acc[mt][nt][2] + b2.x);
            o1.y = act<EPI>(acc[mt][nt][3] + b2.y);
            *(float2*)(Cp + (size_t)r0 * ldc + col) = o0;
            *(float2*)(Cp + (size_t)(r0 + 8) * ldc + col) = o1;
        }
    }
}

// ------------------------- 256x256 transpose (batched) -------------------------
__global__ void transpose_k(const float* __restrict__ src, float* __restrict__ dst)
{
    __shared__ float tile[32][33];
    int z = blockIdx.z;
    const float* Sp = src + (size_t)z * (H * H);
    float* Dp = dst + (size_t)z * (H * H);
    int x0 = blockIdx.x * 32, y0 = blockIdx.y * 32;
    int tx = threadIdx.x, ty = threadIdx.y;
#pragma unroll
    for (int i = 0; i < 32; i += 8) tile[ty + i][tx] = Sp[(y0 + ty + i) * H + x0 + tx];
    __syncthreads();
#pragma unroll
    for (int i = 0; i < 32; i += 8) Dp[(x0 + ty + i) * H + y0 + tx] = tile[tx][ty + i];
}

// ------------------------- attention scores -------------------------
__global__ void __launch_bounds__(256) scores_k(
    const float* __restrict__ Q, const float* __restrict__ Kt)
{
    __shared__ float Ks[32][257];
    int b = blockIdx.x;
    int t = threadIdx.x;
    for (int idx = t; idx < S * H; idx += 256) {
        int k = idx >> 8, c = idx & 255;
        Ks[k][c] = Kt[(size_t)(b * S + k) * H + c];
    }
    __syncthreads();
    int lane = t & 31, w = t >> 5;
#pragma unroll
    for (int qi = 0; qi < 4; qi++) {
        int q = w + qi * 8;
        const float* qrow = Q + (size_t)(b * S + q) * H;
#pragma unroll
        for (int h = 0; h < NH; h++) {
            float accv = 0.f;
#pragma unroll 16
            for (int d = 0; d < HD; d++)
                accv = fmaf(__ldg(qrow + h * HD + d), Ks[lane][h * HD + d], accv);
            g_scores[(size_t)(h * NB + b) * (S * S) + q * S + lane] = accv * 0.125f;
        }
    }
}

// ------------------------- softmax over axis 0 (length 16384) per (q,k) -------------------------
__global__ void __launch_bounds__(256) smax_part_k()
{
    int chunk = blockIdx.x, q = blockIdx.y;
    int t = threadIdx.x, k = t & 31, g = t >> 5;
    float m = -1e30f, sv = 0.f;
    int base = chunk * 512 + g;
    for (int i = 0; i < 64; i++) {
        int bh = base + i * 8;
        float v = g_scores[(size_t)bh * 1024 + q * 32 + k];
        if (v > m) { sv = sv * expf(m - v) + 1.f; m = v; }
        else       { sv += expf(v - m); }
    }
    __shared__ float sm[8][32], ss[8][32];
    sm[g][k] = m; ss[g][k] = sv;
    __syncthreads();
    if (t < 32) {
        float M = sm[0][k];
#pragma unroll
        for (int j = 1; j < 8; j++) M = fmaxf(M, sm[j][k]);
        float Sv = 0.f;
#pragma unroll
        for (int j = 0; j < 8; j++) Sv += ss[j][k] * expf(sm[j][k] - M);
        g_pmax[chunk * 1024 + q * 32 + k] = M;
        g_psum[chunk * 1024 + q * 32 + k] = Sv;
    }
}

__global__ void smax_final_k()
{
    int t = threadIdx.x;
    float M = -1e30f;
    for (int c = 0; c < 32; c++) M = fmaxf(M, g_pmax[c * 1024 + t]);
    float Sv = 0.f;
    for (int c = 0; c < 32; c++) Sv += g_psum[c * 1024 + t] * expf(g_pmax[c * 1024 + t] - M);
    g_smax[t] = M;
    g_ssum[t] = Sv;
}

// ------------------------- weighted-V + Vr + relu + InstanceNorm (fused) -------------------------
__global__ void __launch_bounds__(256) attnout_k(
    const float* __restrict__ V, const float* __restrict__ Vr,
    const float* __restrict__ gamma, const float* __restrict__ beta,
    float* __restrict__ out)
{
    __shared__ float Vsm[32][256];
    __shared__ float wsm[4][32];
    __shared__ float s_stat[2];
    __shared__ float red[2][8];
    __shared__ float s_smax[1024], s_rs[1024];
    int b = blockIdx.x;
    int t = threadIdx.x;
    for (int idx = t; idx < 32 * 256; idx += 256)
        Vsm[idx >> 8][idx & 255] = V[(size_t)(b * 32) * 256 + idx];
    for (int idx = t; idx < 1024; idx += 256) {
        s_smax[idx] = g_smax[idx];
        s_rs[idx]   = 1.f / g_ssum[idx];
    }
    float gam = gamma[t], bet = beta[t];
    int lane = t & 31, wid = t >> 5;
    int hh = t >> 6;
    __syncthreads();
    for (int q = 0; q < 32; q++) {
        if (t < 128) {
            int h = t >> 5, k = t & 31;
            float svv = g_scores[(size_t)(h * NB + b) * 1024 + q * 32 + k];
            wsm[h][k] = expf(svv - s_smax[q * 32 + k]) * s_rs[q * 32 + k];
        }
        __syncthreads();
        float accv = 0.f;
#pragma unroll 8
        for (int k = 0; k < 32; k++)
            accv = fmaf(wsm[hh][k], Vsm[k][t], accv);
        float o = fmaxf(accv + Vr[(size_t)(b * 32 + q) * 256 + t], 0.f);
        float v1 = o, v2 = o * o;
#pragma unroll
        for (int off = 16; off; off >>= 1) {
            v1 += __shfl_down_sync(0xffffffffu, v1, off);
            v2 += __shfl_down_sync(0xffffffffu, v2, off);
        }
        if (lane == 0) { red[0][wid] = v1; red[1][wid] = v2; }
        __syncthreads();
        if (t == 0) {
            float s1 = 0.f, s2 = 0.f;
#pragma unroll
            for (int i = 0; i < 8; i++) { s1 += red[0][i]; s2 += red[1][i]; }
            float mu  = s1 * (1.f / 256.f);
            float var = s2 * (1.f / 256.f) - mu * mu;
            s_stat[0] = mu;
            s_stat[1] = rsqrtf(var + 1e-5f);
        }
        __syncthreads();
        out[(size_t)(b * 32 + q) * 256 + t] = gam * ((o - s_stat[0]) * s_stat[1]) + bet;
        __syncthreads();
    }
}

// ------------------------- GNN helpers -------------------------
__global__ void rowsum_k(const float* __restrict__ X, float* __restrict__ R)
{
    int idx = blockIdx.x * 256 + threadIdx.x;
    int b = idx >> 8, h = idx & 255;
    float accv = 0.f;
#pragma unroll
    for (int s = 0; s < 32; s++)
        accv += X[(size_t)((b << 5) + s) * 256 + h];
    R[idx] = accv;
}

__global__ void sub_bcast_k(const float* __restrict__ R,
                            const float* __restrict__ S1,
                            float* __restrict__ S2)
{
    size_t idx = (size_t)blockIdx.x * 256 + threadIdx.x;
    int row = (int)(idx >> 8);
    int b = row >> 5;
    int h = (int)(idx & 255);
    S2[idx] = R[(b << 8) + h] - S1[idx];
}

__global__ void gru_k(const float* __restrict__ xin, float* __restrict__ xout)
{
    size_t idx = (size_t)blockIdx.x * 256 + threadIdx.x;
    int row = (int)(idx >> 8), c = (int)(idx & 255);
    size_t base = (size_t)row * 768 + c;
    float ir = g_gi[base], iz = g_gi[base + 256], inn = g_gi[base + 512];
    float hr = g_gh[base], hz = g_gh[base + 256], hn = g_gh[base + 512];
    float r = 1.f / (1.f + expf(-(ir + hr)));
    float z = 1.f / (1.f + expf(-(iz + hz)));
    float n = tanhf(inn + r * hn);
    float x = xin[idx];
    xout[idx] = x + (1.f - z) * n + z * x;
}

// ------------------------- final credit head -------------------------
__global__ void __launch_bounds__(256) cred_k(
    const float* __restrict__ M1, const float* __restrict__ M2,
    float* __restrict__ out)
{
    int wid = threadIdx.x >> 5, lane = threadIdx.x & 31;
    int row = blockIdx.x * 8 + wid;
    const float* p1 = M1 + (size_t)row * 256;
    const float* p2 = M2 + (size_t)row * 256;
    float accv = 0.f;
#pragma unroll
    for (int j = 0; j < 8; j++)
        accv = fmaf(p1[lane + j * 32], p2[lane + j * 32], accv);
#pragma unroll
    for (int off = 16; off; off >>= 1)
        accv += __shfl_down_sync(0xffffffffu, accv, off);
    if (lane == 0) out[row] = 1.f / (1.f + expf(-accv));
}

// ------------------------- host orchestration -------------------------
#define SMEM_MM 131072

static void gnn_call(const float* x_in, float* x_out,
                     const float* w1t, const float* mp_b1,
                     const float* w3t, const float* mp_b3,
                     const float* wih, const float* whh,
                     const float* bih, const float* bhh,
                     float* s1, float* s2, float* rowsum)
{
    float *gi, *gh;
    cudaGetSymbolAddress((void**)&gi, g_gi);
    cudaGetSymbolAddress((void**)&gh, g_gh);
    dim3 gs(2, 32, 32);  // n-tiles(256/128), m-tiles(4096/128), sender
    mm_k<0><<<gs, 256, SMEM_MM>>>(x_in, S * H, H, w1t, H * H, mp_b1, H, s1, S * H, H);
    rowsum_k<<<(NB * H) / 256, 256>>>(s1, rowsum);
    sub_bcast_k<<<(BS * H) / 256, 256>>>(rowsum, s1, s2);
    mm_k<0><<<gs, 256, SMEM_MM>>>(s2, S * H, H, w3t, H * H, mp_b3, H, s1, S * H, H);
    mm_k<0><<<dim3(6, 1024), 256, SMEM_MM>>>(s1,   H, 0, wih, 0, bih, 0, gi, 768, 0);
    mm_k<0><<<dim3(6, 1024), 256, SMEM_MM>>>(x_in, H, 0, whh, 0, bhh, 0, gh, 768, 0);
    gru_k<<<(BS * H) / 256, 256>>>(x_in, x_out);
}

extern "C" void kernel_launch(void* const* d_in, const int* in_sizes, int n_in,
                              void* d_out, int out_size)
{
    (void)in_sizes; (void)n_in; (void)out_size;
    const float* inputs  = (const float*)d_in[0];
    const float* embed_w = (const float*)d_in[1];
    const float* embed_b = (const float*)d_in[2];
    const float* wq  = (const float*)d_in[3];
    const float* bq  = (const float*)d_in[4];
    const float* wk  = (const float*)d_in[5];
    const float* bk  = (const float*)d_in[6];
    const float* wv  = (const float*)d_in[7];
    const float* bv  = (const float*)d_in[8];
    const float* wvr = (const float*)d_in[9];
    const float* bvr = (const float*)d_in[10];
    const float* gamma = (const float*)d_in[11];
    const float* beta  = (const float*)d_in[12];
    const float* mp_w1 = (const float*)d_in[13];
    const float* mp_b1 = (const float*)d_in[14];
    const float* mp_w3 = (const float*)d_in[15];
    const float* mp_b3 = (const float*)d_in[16];
    const float* gru_wih = (const float*)d_in[17];
    const float* gru_whh = (const float*)d_in[18];
    const float* gru_bih = (const float*)d_in[19];
    const float* gru_bhh = (const float*)d_in[20];
    const float* mlp1_w = (const float*)d_in[21];
    const float* mlp1_b = (const float*)d_in[22];
    const float* mlp2_w = (const float*)d_in[23];
    const float* mlp2_b = (const float*)d_in[24];

    float *feat, *qb, *kb, *vb, *vrb, *attn, *xa, *xb, *rowsum, *wt7, *w1t, *w3t;
    cudaGetSymbolAddress((void**)&feat,   g_feat);
    cudaGetSymbolAddress((void**)&qb,     g_q);
    cudaGetSymbolAddress((void**)&kb,     g_k);
    cudaGetSymbolAddress((void**)&vb,     g_v);
    cudaGetSymbolAddress((void**)&vrb,    g_vr);
    cudaGetSymbolAddress((void**)&attn,   g_attn);
    cudaGetSymbolAddress((void**)&xa,     g_xa);
    cudaGetSymbolAddress((void**)&xb,     g_xb);
    cudaGetSymbolAddress((void**)&rowsum, g_rowsum);
    cudaGetSymbolAddress((void**)&wt7,    g_wt7);
    cudaGetSymbolAddress((void**)&w1t,    g_w1t);
    cudaGetSymbolAddress((void**)&w3t,    g_w3t);

    cudaFuncSetAttribute(mm_k<0>, cudaFuncAttributeMaxDynamicSharedMemorySize, SMEM_MM);
    cudaFuncSetAttribute(mm_k<1>, cudaFuncAttributeMaxDynamicSharedMemorySize, SMEM_MM);
    cudaFuncSetAttribute(mm_k<2>, cudaFuncAttributeMaxDynamicSharedMemorySize, SMEM_MM);
    cudaFuncSetAttribute(mm_k<3>, cudaFuncAttributeMaxDynamicSharedMemorySize, SMEM_MM);

    float* out_cred = (float*)d_out;
    float* out_fs   = (float*)d_out + BS;   // fs written in place

    // ---- transpose [K,N] weights -> [N,K] for the mma B operand ----
    dim3 tb(32, 8), tg1(8, 8, 1), tg32(8, 8, 32);
    transpose_k<<<tg1, tb>>>(embed_w, wt7 + 0 * H * H);
    transpose_k<<<tg1, tb>>>(wq,      wt7 + 1 * H * H);
    transpose_k<<<tg1, tb>>>(wk,      wt7 + 2 * H * H);
    transpose_k<<<tg1, tb>>>(wv,      wt7 + 3 * H * H);
    transpose_k<<<tg1, tb>>>(wvr,     wt7 + 4 * H * H);
    transpose_k<<<tg1, tb>>>(mlp1_w,  wt7 + 5 * H * H);
    transpose_k<<<tg1, tb>>>(mlp2_w,  wt7 + 6 * H * H);
    transpose_k<<<tg32, tb>>>(mp_w1, w1t);
    transpose_k<<<tg32, tb>>>(mp_w3, w3t);

    dim3 g2(2, 1024);
    // feat = tanh(inputs @ embed_w + b)
    mm_k<2><<<g2, 256, SMEM_MM>>>(inputs, H, 0, wt7 + 0 * H * H, 0, embed_b, 0, feat, H, 0);
    // Q/K/V/Vr = relu(feat @ W + b)
    mm_k<1><<<g2, 256, SMEM_MM>>>(feat, H, 0, wt7 + 1 * H * H, 0, bq,  0, qb,  H, 0);
    mm_k<1><<<g2, 256, SMEM_MM>>>(feat, H, 0, wt7 + 2 * H * H, 0, bk,  0, kb,  H, 0);
    mm_k<1><<<g2, 256, SMEM_MM>>>(feat, H, 0, wt7 + 3 * H * H, 0, bv,  0, vb,  H, 0);
    mm_k<1><<<g2, 256, SMEM_MM>>>(feat, H, 0, wt7 + 4 * H * H, 0, bvr, 0, vrb, H, 0);
    // attention
    scores_k<<<NB, 256>>>(qb, kb);
    smax_part_k<<<dim3(32, 32), 256>>>();
    smax_final_k<<<1, 1024>>>();
    attnout_k<<<NB, 256>>>(vb, vrb, gamma, beta, attn);
    // GNN x4 (first output = fs, written directly to d_out region)
    gnn_call(attn,   out_fs, w1t, mp_b1, w3t, mp_b3, gru_wih, gru_whh, gru_bih, gru_bhh, qb, kb, rowsum);
    gnn_call(out_fs, xa,     w1t, mp_b1, w3t, mp_b3, gru_wih, gru_whh, gru_bih, gru_bhh, qb, kb, rowsum);
    gnn_call(xa,     xb,     w1t, mp_b1, w3t, mp_b3, gru_wih, gru_whh, gru_bih, gru_bhh, qb, kb, rowsum);
    gnn_call(xb,     xa,     w1t, mp_b1, w3t, mp_b3, gru_wih, gru_whh, gru_bih, gru_bhh, qb, kb, rowsum);
    // head: m1 = tanh(fs3@mlp1), m2 = leaky(fs3@mlp2), cred = sigmoid(sum(m1*m2))
    mm_k<2><<<g2, 256, SMEM_MM>>>(xa, H, 0, wt7 + 5 * H * H, 0, mlp1_b, 0, qb, H, 0);
    mm_k<3><<<g2, 256, SMEM_MM>>>(xa, H, 0, wt7 + 6 * H * H, 0, mlp2_b, 0, kb, H, 0);
    cred_k<<<BS / 8, 256>>>(qb, kb, out_cred);
}

// round 12
// speedup vs baseline: 1.9439x; 1.6160x over previous
#include <cuda_runtime.h>
#include <cuda_fp16.h>
#include <cstdint>
#include <math.h>

#define H 256
#define S 32
#define NB 4096            // batch
#define BS (NB * S)        // 131072 flattened rows
#define NH 4
#define HD 64
#define BH (NH * NB)       // 16384 (head*batch axis length)

// ------------------------- scratch (__device__ globals) -------------------------
__device__ float g_feat[BS * H];
__device__ float g_q[BS * H];
__device__ float g_k[BS * H];
__device__ float g_v[BS * H];
__device__ float g_vr[BS * H];
__device__ float g_attn[BS * H];
__device__ float g_xa[BS * H];
__device__ float g_xb[BS * H];
__device__ float g_scores[(size_t)BH * S * S];   // [bh][q][k]
__device__ float g_pmax[32 * S * S];
__device__ float g_psum[32 * S * S];
__device__ float g_smax[S * S];
__device__ float g_ssum[S * S];
__device__ float g_gi[(size_t)BS * 3 * H];
__device__ float g_gh[(size_t)BS * 3 * H];
// transposed weights ([N,K] layout for the mma B operand)
__device__ float g_wt7[7 * H * H];        // embed, wq, wk, wv, wvr, mlp1, mlp2
__device__ float g_w1t[S * H * H];
__device__ float g_w3t[S * H * H];

// ------------------------- helpers -------------------------
// split (x,y) into packed fp16 hi + fp16 lo (combined ~21-22 mantissa bits)
__device__ __forceinline__ void split2(float x, float y, uint32_t& h, uint32_t& l) {
    __half2 hh = __floats2half2_rn(x, y);
    float2 hf = __half22float2(hh);
    __half2 ll = __floats2half2_rn(x - hf.x, y - hf.y);
    h = *reinterpret_cast<uint32_t*>(&hh);
    l = *reinterpret_cast<uint32_t*>(&ll);
}

// D += A@B  (m16n8k16 fp16 in, fp32 accum, row.col)
__device__ __forceinline__ void mma16(float* d, const uint32_t* a, const uint32_t* b) {
    asm volatile("mma.sync.aligned.m16n8k16.row.col.f32.f16.f16.f32 "
        "{%0,%1,%2,%3}, {%4,%5,%6,%7}, {%8,%9}, {%0,%1,%2,%3};"
        : "+f"(d[0]), "+f"(d[1]), "+f"(d[2]), "+f"(d[3])
        : "r"(a[0]), "r"(a[1]), "r"(a[2]), "r"(a[3]), "r"(b[0]), "r"(b[1]));
}

// ------------------------- epilogue activations -------------------------
template <int EPI>
__device__ __forceinline__ float act(float v) {
    if (EPI == 1) return fmaxf(v, 0.f);           // relu
    if (EPI == 2) return tanhf(v);                // tanh
    if (EPI == 3) return v > 0.f ? v : 0.01f * v; // leaky relu
    return v;
}

// ------------------------- mma.sync fp16x3 GEMM -------------------------
// C[z][m0+0..127, n0+0..127] = act( A[z] @ Bt[z]^T + bias[z] )
// A row-major [M, K=256] (lda floats, z-stride az)
// Bt row-major [N, K=256] (ldb = 256, z-stride bz)
//
// smem (dynamic, 64 KB of u32 words, values are packed half2 k-pairs):
//   A: (p*2+comp)*2048          comp 0 = fp16 hi, comp 1 = fp16 lo
//   B: 8192 + (p*2+comp)*2048
// Word layout (k-chunk = 32 floats = 2 k16 steps):
//   pair index p (0..7) within a k16 step maps to word slot
//   w(p) = (2*(p&3) + (p>>2)) ^ (ks<<1)      (ks-xor kills STS/LDS conflicts)
//   A word: (mt*4 + ks*2 + r8)*64 + g*8 + w     (mt=row>>4, r8=(row&15)>>3, g=row&7)
//   B word: (nti*2 + ks)*64 + n8*8 + w          (nti=row>>3, n8=row&7)
// Thread(g,cl) fragment loads are uint2 at slot (2cl)^(2ks): gives pairs (cl, cl+4)
// = exactly the m16n8k16 (a0,a2)/(a1,a3)/(b0,b1) fragment elements.
template <int EPI>
__global__ void __launch_bounds__(256) mm_k(
    const float* __restrict__ A, long lda, long az,
    const float* __restrict__ B, long bz,
    const float* __restrict__ bias, long biz,
    float* __restrict__ C, long ldc, long cz)
{
    extern __shared__ uint32_t smem[];
    const int t = threadIdx.x;
    const int m0 = blockIdx.y * 128;
    const int n0 = blockIdx.x * 128;
    const int z  = blockIdx.z;
    const float* Ap = A + (size_t)z * az + (size_t)m0 * lda;
    const float* Bp = B + (size_t)z * bz + (size_t)n0 * 256;
    const float* bp = bias + (size_t)z * biz + n0;
    float* Cp = C + (size_t)z * cz + (size_t)m0 * ldc + n0;

    const int lane = t & 31, w = t >> 5;
    const int wM = w >> 2, wN = w & 3;           // warp grid 2(M) x 4(N)
    const int g = lane >> 2, cl = lane & 3;

    float acc[4][4][4];
#pragma unroll
    for (int i = 0; i < 4; i++)
#pragma unroll
        for (int j = 0; j < 4; j++)
#pragma unroll
            for (int k = 0; k < 4; k++) acc[i][j][k] = 0.f;

    float4 va[4], vb[4];

    // ---- staging load (gmem -> regs) for k-chunk base kb ----
    auto ldstage = [&](int kb) {
#pragma unroll
        for (int i = 0; i < 4; i++) {
            int idx = t + i * 256, row = idx >> 3, f4 = idx & 7;
            va[i] = *(const float4*)(Ap + (size_t)row * lda + kb + f4 * 4);
            vb[i] = *(const float4*)(Bp + (size_t)row * 256 + kb + f4 * 4);
        }
    };
    // ---- regs -> smem (fp16 hi/lo split, fragment-major layout) ----
    auto ststage = [&](int p) {
        uint32_t* A0 = smem + (p * 2 + 0) * 2048;
        uint32_t* A1 = smem + (p * 2 + 1) * 2048;
        uint32_t* B0 = smem + 8192 + (p * 2 + 0) * 2048;
        uint32_t* B1 = smem + 8192 + (p * 2 + 1) * 2048;
#pragma unroll
        for (int i = 0; i < 4; i++) {
            int idx = t + i * 256, row = idx >> 3, f4 = idx & 7;
            int ks = f4 >> 2, j = f4 & 3;
            // slots for pairs 2j and 2j+1 within the k16 step
            int w0 = (2 * ((2 * j) & 3) + ((2 * j) >> 2)) ^ (ks << 1);
            int w1 = (2 * ((2 * j + 1) & 3) + ((2 * j + 1) >> 2)) ^ (ks << 1);
            uint32_t h0, l0, h1, l1;
            // A
            {
                int mt = row >> 4, r = row & 15;
                int seg = (mt * 4 + ks * 2 + (r >> 3)) * 64 + (r & 7) * 8;
                split2(va[i].x, va[i].y, h0, l0);
                split2(va[i].z, va[i].w, h1, l1);
                A0[seg + w0] = h0; A1[seg + w0] = l0;
                A0[seg + w1] = h1; A1[seg + w1] = l1;
            }
            // B
            {
                int nti = row >> 3, n8 = row & 7;
                int seg = (nti * 2 + ks) * 64 + n8 * 8;
                split2(vb[i].x, vb[i].y, h0, l0);
                split2(vb[i].z, vb[i].w, h1, l1);
                B0[seg + w0] = h0; B1[seg + w0] = l0;
                B0[seg + w1] = h1; B1[seg + w1] = l1;
            }
        }
    };
    // ---- one k32 chunk: 2 k16 steps of fp16x3 mma ----
    auto compute = [&](int p) {
        const uint32_t* A0 = smem + (p * 2 + 0) * 2048;
        const uint32_t* A1 = smem + (p * 2 + 1) * 2048;
        const uint32_t* B0 = smem + 8192 + (p * 2 + 0) * 2048;
        const uint32_t* B1 = smem + 8192 + (p * 2 + 1) * 2048;
#pragma unroll
        for (int ks = 0; ks < 2; ks++) {
            const int cx = (cl * 2) ^ (ks << 1);
            uint32_t a0[4][4], a1[4][4], b0[4][2], b1[4][2];
#pragma unroll
            for (int mt = 0; mt < 4; mt++) {
                int mtg = wM * 4 + mt;
                int off = (mtg * 4 + ks * 2) * 64 + g * 8 + cx;
                uint2 lo0 = *(const uint2*)(A0 + off);
                uint2 hi0 = *(const uint2*)(A0 + off + 64);
                a0[mt][0] = lo0.x; a0[mt][2] = lo0.y;
                a0[mt][1] = hi0.x; a0[mt][3] = hi0.y;
                uint2 lo1 = *(const uint2*)(A1 + off);
                uint2 hi1 = *(const uint2*)(A1 + off + 64);
                a1[mt][0] = lo1.x; a1[mt][2] = lo1.y;
                a1[mt][1] = hi1.x; a1[mt][3] = hi1.y;
            }
#pragma unroll
            for (int nt = 0; nt < 4; nt++) {
                int ntg = wN * 4 + nt;
                int off = (ntg * 2 + ks) * 64 + g * 8 + cx;
                uint2 v0 = *(const uint2*)(B0 + off);
                b0[nt][0] = v0.x; b0[nt][1] = v0.y;
                uint2 v1 = *(const uint2*)(B1 + off);
                b1[nt][0] = v1.x; b1[nt][1] = v1.y;
            }
#pragma unroll
            for (int mt = 0; mt < 4; mt++)
#pragma unroll
                for (int nt = 0; nt < 4; nt++) {
                    mma16(acc[mt][nt], a0[mt], b0[nt]);   // hi*hi
                    mma16(acc[mt][nt], a0[mt], b1[nt]);   // hi*lo
                    mma16(acc[mt][nt], a1[mt], b0[nt]);   // lo*hi
                }
        }
    };

    // ---- mainloop: 8 chunks, double buffered ----
    ldstage(0);
    ststage(0);
    __syncthreads();
    int p = 0;
    for (int ch = 0; ch < 8; ch++) {
        if (ch < 7) ldstage((ch + 1) * 32);
        compute(p);
        if (ch < 7) {
            ststage(p ^ 1);
            __syncthreads();
            p ^= 1;
        }
    }

    // ---- epilogue: bias + act, float2 stores ----
    const int wm = wM * 64, wn = wN * 32;
#pragma unroll
    for (int mt = 0; mt < 4; mt++) {
        int r0 = wm + mt * 16 + g;
#pragma unroll
        for (int nt = 0; nt < 4; nt++) {
            int col = wn + nt * 8 + (cl << 1);
            float2 b2 = *(const float2*)(bp + col);
            float2 o0, o1;
            o0.x = act<EPI>(acc[mt][nt][0] + b2.x);
            o0.y = act<EPI>(acc[mt][nt][1] + b2.y);
            o1.x = act<EPI>(acc[mt][nt][2] + b2.x);
            o1.y = act<EPI>(acc[mt][nt][3] + b2.y);
            *(float2*)(Cp + (size_t)r0 * ldc + col) = o0;
            *(float2*)(Cp + (size_t)(r0 + 8) * ldc + col) = o1;
        }
    }
}

// ------------------------- 256x256 transpose (batched) -------------------------
__global__ void transpose_k(const float* __restrict__ src, float* __restrict__ dst)
{
    __shared__ float tile[32][33];
    int z = blockIdx.z;
    const float* Sp = src + (size_t)z * (H * H);
    float* Dp = dst + (size_t)z * (H * H);
    int x0 = blockIdx.x * 32, y0 = blockIdx.y * 32;
    int tx = threadIdx.x, ty = threadIdx.y;
#pragma unroll
    for (int i = 0; i < 32; i += 8) tile[ty + i][tx] = Sp[(y0 + ty + i) * H + x0 + tx];
    __syncthreads();
#pragma unroll
    for (int i = 0; i < 32; i += 8) Dp[(x0 + ty + i) * H + y0 + tx] = tile[tx][ty + i];
}

// ------------------------- attention scores -------------------------
__global__ void __launch_bounds__(256) scores_k(
    const float* __restrict__ Q, const float* __restrict__ Kt)
{
    __shared__ float Ks[32][257];
    int b = blockIdx.x;
    int t = threadIdx.x;
    for (int idx = t; idx < S * H; idx += 256) {
        int k = idx >> 8, c = idx & 255;
        Ks[k][c] = Kt[(size_t)(b * S + k) * H + c];
    }
    __syncthreads();
    int lane = t & 31, w = t >> 5;
#pragma unroll
    for (int qi = 0; qi < 4; qi++) {
        int q = w + qi * 8;
        const float* qrow = Q + (size_t)(b * S + q) * H;
#pragma unroll
        for (int h = 0; h < NH; h++) {
            float accv = 0.f;
#pragma unroll 16
            for (int d = 0; d < HD; d++)
                accv = fmaf(__ldg(qrow + h * HD + d), Ks[lane][h * HD + d], accv);
            g_scores[(size_t)(h * NB + b) * (S * S) + q * S + lane] = accv * 0.125f;
        }
    }
}

// ------------------------- softmax over axis 0 (length 16384) per (q,k) -------------------------
__global__ void __launch_bounds__(256) smax_part_k()
{
    int chunk = blockIdx.x, q = blockIdx.y;
    int t = threadIdx.x, k = t & 31, g = t >> 5;
    float m = -1e30f, sv = 0.f;
    int base = chunk * 512 + g;
    for (int i = 0; i < 64; i++) {
        int bh = base + i * 8;
        float v = g_scores[(size_t)bh * 1024 + q * 32 + k];
        if (v > m) { sv = sv * expf(m - v) + 1.f; m = v; }
        else       { sv += expf(v - m); }
    }
    __shared__ float sm[8][32], ss[8][32];
    sm[g][k] = m; ss[g][k] = sv;
    __syncthreads();
    if (t < 32) {
        float M = sm[0][k];
#pragma unroll
        for (int j = 1; j < 8; j++) M = fmaxf(M, sm[j][k]);
        float Sv = 0.f;
#pragma unroll
        for (int j = 0; j < 8; j++) Sv += ss[j][k] * expf(sm[j][k] - M);
        g_pmax[chunk * 1024 + q * 32 + k] = M;
        g_psum[chunk * 1024 + q * 32 + k] = Sv;
    }
}

__global__ void smax_final_k()
{
    int t = threadIdx.x;
    float M = -1e30f;
    for (int c = 0; c < 32; c++) M = fmaxf(M, g_pmax[c * 1024 + t]);
    float Sv = 0.f;
    for (int c = 0; c < 32; c++) Sv += g_psum[c * 1024 + t] * expf(g_pmax[c * 1024 + t] - M);
    g_smax[t] = M;
    g_ssum[t] = Sv;
}

// ------------------------- weighted-V + Vr + relu + InstanceNorm (fused) -------------------------
__global__ void __launch_bounds__(256) attnout_k(
    const float* __restrict__ V, const float* __restrict__ Vr,
    const float* __restrict__ gamma, const float* __restrict__ beta,
    float* __restrict__ out)
{
    __shared__ float Vsm[32][256];
    __shared__ float wsm[4][32];
    __shared__ float s_stat[2];
    __shared__ float red[2][8];
    __shared__ float s_smax[1024], s_rs[1024];
    int b = blockIdx.x;
    int t = threadIdx.x;
    for (int idx = t; idx < 32 * 256; idx += 256)
        Vsm[idx >> 8][idx & 255] = V[(size_t)(b * 32) * 256 + idx];
    for (int idx = t; idx < 1024; idx += 256) {
        s_smax[idx] = g_smax[idx];
        s_rs[idx]   = 1.f / g_ssum[idx];
    }
    float gam = gamma[t], bet = beta[t];
    int lane = t & 31, wid = t >> 5;
    int hh = t >> 6;
    __syncthreads();
    for (int q = 0; q < 32; q++) {
        if (t < 128) {
            int h = t >> 5, k = t & 31;
            float svv = g_scores[(size_t)(h * NB + b) * 1024 + q * 32 + k];
            wsm[h][k] = expf(svv - s_smax[q * 32 + k]) * s_rs[q * 32 + k];
        }
        __syncthreads();
        float accv = 0.f;
#pragma unroll 8
        for (int k = 0; k < 32; k++)
            accv = fmaf(wsm[hh][k], Vsm[k][t], accv);
        float o = fmaxf(accv + Vr[(size_t)(b * 32 + q) * 256 + t], 0.f);
        float v1 = o, v2 = o * o;
#pragma unroll
        for (int off = 16; off; off >>= 1) {
            v1 += __shfl_down_sync(0xffffffffu, v1, off);
            v2 += __shfl_down_sync(0xffffffffu, v2, off);
        }
        if (lane == 0) { red[0][wid] = v1; red[1][wid] = v2; }
        __syncthreads();
        if (t == 0) {
            float s1 = 0.f, s2 = 0.f;
#pragma unroll
            for (int i = 0; i < 8; i++) { s1 += red[0][i]; s2 += red[1][i]; }
            float mu  = s1 * (1.f / 256.f);
            float var = s2 * (1.f / 256.f) - mu * mu;
            s_stat[0] = mu;
            s_stat[1] = rsqrtf(var + 1e-5f);
        }
        __syncthreads();
        out[(size_t)(b * 32 + q) * 256 + t] = gam * ((o - s_stat[0]) * s_stat[1]) + bet;
        __syncthreads();
    }
}

// ------------------------- GNN helpers -------------------------
// fused rowsum + subtract-broadcast: S2[b,s,h] = (sum_s' S1[b,s',h]) - S1[b,s,h]
__global__ void __launch_bounds__(256) msg_sub_k(
    const float* __restrict__ S1, float* __restrict__ S2)
{
    int b = blockIdx.x, h = threadIdx.x;
    const float* src = S1 + (size_t)(b << 5) * 256 + h;
    float v[32];
    float accv = 0.f;
#pragma unroll
    for (int s = 0; s < 32; s++) {
        v[s] = src[s * 256];
        accv += v[s];
    }
    float* dst = S2 + (size_t)(b << 5) * 256 + h;
#pragma unroll
    for (int s = 0; s < 32; s++)
        dst[s * 256] = accv - v[s];
}

__global__ void gru_k(const float* __restrict__ xin, float* __restrict__ xout)
{
    size_t idx = (size_t)blockIdx.x * 256 + threadIdx.x;
    int row = (int)(idx >> 8), c = (int)(idx & 255);
    size_t base = (size_t)row * 768 + c;
    float ir = g_gi[base], iz = g_gi[base + 256], inn = g_gi[base + 512];
    float hr = g_gh[base], hz = g_gh[base + 256], hn = g_gh[base + 512];
    float r = 1.f / (1.f + expf(-(ir + hr)));
    float z = 1.f / (1.f + expf(-(iz + hz)));
    float n = tanhf(inn + r * hn);
    float x = xin[idx];
    xout[idx] = x + (1.f - z) * n + z * x;
}

// ------------------------- final credit head -------------------------
__global__ void __launch_bounds__(256) cred_k(
    const float* __restrict__ M1, const float* __restrict__ M2,
    float* __restrict__ out)
{
    int wid = threadIdx.x >> 5, lane = threadIdx.x & 31;
    int row = blockIdx.x * 8 + wid;
    const float* p1 = M1 + (size_t)row * 256;
    const float* p2 = M2 + (size_t)row * 256;
    float accv = 0.f;
#pragma unroll
    for (int j = 0; j < 8; j++)
        accv = fmaf(p1[lane + j * 32], p2[lane + j * 32], accv);
#pragma unroll
    for (int off = 16; off; off >>= 1)
        accv += __shfl_down_sync(0xffffffffu, accv, off);
    if (lane == 0) out[row] = 1.f / (1.f + expf(-accv));
}

// ------------------------- host orchestration -------------------------
#define SMEM_MM 65536

static void gnn_call(const float* x_in, float* x_out,
                     const float* w1t, const float* mp_b1,
                     const float* w3t, const float* mp_b3,
                     const float* wih, const float* whh,
                     const float* bih, const float* bhh,
                     float* s1, float* s2)
{
    float *gi, *gh;
    cudaGetSymbolAddress((void**)&gi, g_gi);
    cudaGetSymbolAddress((void**)&gh, g_gh);
    dim3 gs(2, 32, 32);  // n-tiles(256/128), m-tiles(4096/128), sender
    mm_k<0><<<gs, 256, SMEM_MM>>>(x_in, S * H, H, w1t, H * H, mp_b1, H, s1, S * H, H);
    msg_sub_k<<<NB, 256>>>(s1, s2);
    mm_k<0><<<gs, 256, SMEM_MM>>>(s2, S * H, H, w3t, H * H, mp_b3, H, s1, S * H, H);
    mm_k<0><<<dim3(6, 1024), 256, SMEM_MM>>>(s1,   H, 0, wih, 0, bih, 0, gi, 768, 0);
    mm_k<0><<<dim3(6, 1024), 256, SMEM_MM>>>(x_in, H, 0, whh, 0, bhh, 0, gh, 768, 0);
    gru_k<<<(BS * H) / 256, 256>>>(x_in, x_out);
}

extern "C" void kernel_launch(void* const* d_in, const int* in_sizes, int n_in,
                              void* d_out, int out_size)
{
    (void)in_sizes; (void)n_in; (void)out_size;
    const float* inputs  = (const float*)d_in[0];
    const float* embed_w = (const float*)d_in[1];
    const float* embed_b = (const float*)d_in[2];
    const float* wq  = (const float*)d_in[3];
    const float* bq  = (const float*)d_in[4];
    const float* wk  = (const float*)d_in[5];
    const float* bk  = (const float*)d_in[6];
    const float* wv  = (const float*)d_in[7];
    const float* bv  = (const float*)d_in[8];
    const float* wvr = (const float*)d_in[9];
    const float* bvr = (const float*)d_in[10];
    const float* gamma = (const float*)d_in[11];
    const float* beta  = (const float*)d_in[12];
    const float* mp_w1 = (const float*)d_in[13];
    const float* mp_b1 = (const float*)d_in[14];
    const float* mp_w3 = (const float*)d_in[15];
    const float* mp_b3 = (const float*)d_in[16];
    const float* gru_wih = (const float*)d_in[17];
    const float* gru_whh = (const float*)d_in[18];
    const float* gru_bih = (const float*)d_in[19];
    const float* gru_bhh = (const float*)d_in[20];
    const float* mlp1_w = (const float*)d_in[21];
    const float* mlp1_b = (const float*)d_in[22];
    const float* mlp2_w = (const float*)d_in[23];
    const float* mlp2_b = (const float*)d_in[24];

    float *feat, *qb, *kb, *vb, *vrb, *attn, *xa, *xb, *wt7, *w1t, *w3t;
    cudaGetSymbolAddress((void**)&feat,   g_feat);
    cudaGetSymbolAddress((void**)&qb,     g_q);
    cudaGetSymbolAddress((void**)&kb,     g_k);
    cudaGetSymbolAddress((void**)&vb,     g_v);
    cudaGetSymbolAddress((void**)&vrb,    g_vr);
    cudaGetSymbolAddress((void**)&attn,   g_attn);
    cudaGetSymbolAddress((void**)&xa,     g_xa);
    cudaGetSymbolAddress((void**)&xb,     g_xb);
    cudaGetSymbolAddress((void**)&wt7,    g_wt7);
    cudaGetSymbolAddress((void**)&w1t,    g_w1t);
    cudaGetSymbolAddress((void**)&w3t,    g_w3t);

    cudaFuncSetAttribute(mm_k<0>, cudaFuncAttributeMaxDynamicSharedMemorySize, SMEM_MM);
    cudaFuncSetAttribute(mm_k<1>, cudaFuncAttributeMaxDynamicSharedMemorySize, SMEM_MM);
    cudaFuncSetAttribute(mm_k<2>, cudaFuncAttributeMaxDynamicSharedMemorySize, SMEM_MM);
    cudaFuncSetAttribute(mm_k<3>, cudaFuncAttributeMaxDynamicSharedMemorySize, SMEM_MM);

    float* out_cred = (float*)d_out;
    float* out_fs   = (float*)d_out + BS;   // fs written in place

    // ---- transpose [K,N] weights -> [N,K] for the mma B operand ----
    dim3 tb(32, 8), tg1(8, 8, 1), tg32(8, 8, 32);
    transpose_k<<<tg1, tb>>>(embed_w, wt7 + 0 * H * H);
    transpose_k<<<tg1, tb>>>(wq,      wt7 + 1 * H * H);
    transpose_k<<<tg1, tb>>>(wk,      wt7 + 2 * H * H);
    transpose_k<<<tg1, tb>>>(wv,      wt7 + 3 * H * H);
    transpose_k<<<tg1, tb>>>(wvr,     wt7 + 4 * H * H);
    transpose_k<<<tg1, tb>>>(mlp1_w,  wt7 + 5 * H * H);
    transpose_k<<<tg1, tb>>>(mlp2_w,  wt7 + 6 * H * H);
    transpose_k<<<tg32, tb>>>(mp_w1, w1t);
    transpose_k<<<tg32, tb>>>(mp_w3, w3t);

    dim3 g2(2, 1024);
    // feat = tanh(inputs @ embed_w + b)
    mm_k<2><<<g2, 256, SMEM_MM>>>(inputs, H, 0, wt7 + 0 * H * H, 0, embed_b, 0, feat, H, 0);
    // Q/K/V/Vr = relu(feat @ W + b)
    mm_k<1><<<g2, 256, SMEM_MM>>>(feat, H, 0, wt7 + 1 * H * H, 0, bq,  0, qb,  H, 0);
    mm_k<1><<<g2, 256, SMEM_MM>>>(feat, H, 0, wt7 + 2 * H * H, 0, bk,  0, kb,  H, 0);
    mm_k<1><<<g2, 256, SMEM_MM>>>(feat, H, 0, wt7 + 3 * H * H, 0, bv,  0, vb,  H, 0);
    mm_k<1><<<g2, 256, SMEM_MM>>>(feat, H, 0, wt7 + 4 * H * H, 0, bvr, 0, vrb, H, 0);
    // attention
    scores_k<<<NB, 256>>>(qb, kb);
    smax_part_k<<<dim3(32, 32), 256>>>();
    smax_final_k<<<1, 1024>>>();
    attnout_k<<<NB, 256>>>(vb, vrb, gamma, beta, attn);
    // GNN x4 (first output = fs, written directly to d_out region)
    gnn_call(attn,   out_fs, w1t, mp_b1, w3t, mp_b3, gru_wih, gru_whh, gru_bih, gru_bhh, qb, kb);
    gnn_call(out_fs, xa,     w1t, mp_b1, w3t, mp_b3, gru_wih, gru_whh, gru_bih, gru_bhh, qb, kb);
    gnn_call(xa,     xb,     w1t, mp_b1, w3t, mp_b3, gru_wih, gru_whh, gru_bih, gru_bhh, qb, kb);
    gnn_call(xb,     xa,     w1t, mp_b1, w3t, mp_b3, gru_wih, gru_whh, gru_bih, gru_bhh, qb, kb);
    // head: m1 = tanh(fs3@mlp1), m2 = leaky(fs3@mlp2), cred = sigmoid(sum(m1*m2))
    mm_k<2><<<g2, 256, SMEM_MM>>>(xa, H, 0, wt7 + 5 * H * H, 0, mlp1_b, 0, qb, H, 0);
    mm_k<3><<<g2, 256, SMEM_MM>>>(xa, H, 0, wt7 + 6 * H * H, 0, mlp2_b, 0, kb, H, 0);
    cred_k<<<BS / 8, 256>>>(qb, kb, out_cred);
}

// round 14
// speedup vs baseline: 1.9820x; 1.0196x over previous
#include <cuda_runtime.h>
#include <cuda_fp16.h>
#include <cstdint>
#include <math.h>

#define H 256
#define S 32
#define NB 4096            // batch
#define BS (NB * S)        // 131072 flattened rows
#define NH 4
#define HD 64
#define BH (NH * NB)       // 16384 (head*batch axis length)

// ------------------------- scratch (__device__ globals) -------------------------
__device__ float g_feat[BS * H];
__device__ float g_q[BS * H];
__device__ float g_k[BS * H];
__device__ float g_v[BS * H];
__device__ float g_vr[BS * H];
__device__ float g_attn[BS * H];
__device__ float g_xa[BS * H];
__device__ float g_xb[BS * H];
__device__ float g_scores[(size_t)BH * S * S];   // [bh][q][k]
__device__ float g_pmax[32 * S * S];
__device__ float g_psum[32 * S * S];
__device__ float g_smax[S * S];
__device__ float g_ssum[S * S];
__device__ float g_rowsum[NB * H];
__device__ __half g_gi[(size_t)BS * 3 * H];
__device__ __half g_gh[(size_t)BS * 3 * H];

// pre-split, pre-swizzled weights (packed half2 words, hi and lo components)
// layout: per (z, n-tile, k-chunk) block of 2048 words matching the mm_k smem image
#define W7_OFF   0u              // 7 matrices [K,N]->..., 32768 words each
#define W1_OFF   229376u         // 32 z, 32768 words each
#define W3_OFF   1277952u
#define WIH_OFF  2326528u        // N=768: 6 tiles -> 98304 words
#define WHH_OFF  2424832u
#define WTOT     2523136u
__device__ uint32_t g_wbh[WTOT];
__device__ uint32_t g_wbl[WTOT];

// ------------------------- helpers -------------------------
// split (x,y) into packed fp16 hi + fp16 lo (combined ~21-22 mantissa bits)
__device__ __forceinline__ void split2(float x, float y, uint32_t& h, uint32_t& l) {
    __half2 hh = __floats2half2_rn(x, y);
    float2 hf = __half22float2(hh);
    __half2 ll = __floats2half2_rn(x - hf.x, y - hf.y);
    h = *reinterpret_cast<uint32_t*>(&hh);
    l = *reinterpret_cast<uint32_t*>(&ll);
}

// D += A@B  (m16n8k16 fp16 in, fp32 accum, row.col)
__device__ __forceinline__ void mma16(float* d, const uint32_t* a, const uint32_t* b) {
    asm volatile("mma.sync.aligned.m16n8k16.row.col.f32.f16.f16.f32 "
        "{%0,%1,%2,%3}, {%4,%5,%6,%7}, {%8,%9}, {%0,%1,%2,%3};"
        : "+f"(d[0]), "+f"(d[1]), "+f"(d[2]), "+f"(d[3])
        : "r"(a[0]), "r"(a[1]), "r"(a[2]), "r"(a[3]), "r"(b[0]), "r"(b[1]));
}

// ------------------------- epilogue activations -------------------------
template <int EPI>
__device__ __forceinline__ float act(float v) {
    if (EPI == 1) return fmaxf(v, 0.f);           // relu
    if (EPI == 2) return tanhf(v);                // tanh
    if (EPI == 3) return v > 0.f ? v : 0.01f * v; // leaky relu
    return v;
}

// ------------------------- weight prep: fp32 -> swizzled fp16 hi/lo blocks ----
// Target word W in a 2048-word (tile, chunk) block encodes:
//   nti=W>>7, ks=(W>>6)&1, n8=(W>>3)&7, w=W&7 ; wp=w^(ks<<1); p=(wp>>1)|((wp&1)<<2)
//   row n = tile*128+nti*8+n8 ; cols k0 = chunk*32+ks*16+2p, k0+1
// TRANS=1: src is [K, N] row-major ([k,n] = k*N+n); TRANS=0: src is [N, 256].
__global__ void wprep_k(const float* __restrict__ src,
                        uint32_t* __restrict__ dh, uint32_t* __restrict__ dl,
                        int N, int trans)
{
    int z = blockIdx.z, tile = blockIdx.y, c = blockIdx.x;
    const float* Sp = src + (size_t)z * ((size_t)N * 256);
    size_t base = ((size_t)z * (N / 128) + tile) * 16384 + (size_t)c * 2048;
    for (int W = threadIdx.x; W < 2048; W += 256) {
        int nti = W >> 7, ks = (W >> 6) & 1, n8 = (W >> 3) & 7, w = W & 7;
        int wp = w ^ (ks << 1);
        int p = (wp >> 1) | ((wp & 1) << 2);
        int n = tile * 128 + nti * 8 + n8;
        int k0 = c * 32 + ks * 16 + 2 * p;
        float v0, v1;
        if (trans) { v0 = Sp[(size_t)k0 * N + n]; v1 = Sp[(size_t)(k0 + 1) * N + n]; }
        else       { v0 = Sp[(size_t)n * 256 + k0]; v1 = Sp[(size_t)n * 256 + k0 + 1]; }
        uint32_t h, l;
        split2(v0, v1, h, l);
        dh[base + W] = h;
        dl[base + W] = l;
    }
}

// ------------------------- mma.sync fp16x3 GEMM -------------------------
// C[z][m0+0..127, n0+0..127] = act( A'[z] @ Bt[z]^T + bias[z] )
//   A row-major [M, K=256]; if SUBR, A' = R[row, k] - A (GEMM row == batch index)
//   B given pre-split/pre-swizzled (g_wbh/g_wbl blocks, word stride bzw per z)
// OUTH: write __half output (ldc in halves), else float.
template <int EPI, bool OUTH, bool SUBR>
__global__ void __launch_bounds__(256) mm_k(
    const float* __restrict__ A, long lda, long az,
    const uint32_t* __restrict__ Bh, const uint32_t* __restrict__ Bl, long bzw,
    const float* __restrict__ bias, long biz,
    void* __restrict__ Cv, long ldc, long cz,
    const float* __restrict__ R)
{
    extern __shared__ uint32_t smem[];
    const int t = threadIdx.x;
    const int m0 = blockIdx.y * 128;
    const int n0 = blockIdx.x * 128;
    const int z  = blockIdx.z;
    const float* Ap = A + (size_t)z * az + (size_t)m0 * lda;
    const uint32_t* Bhp = Bh + (size_t)z * bzw + (size_t)(n0 >> 7) * 16384;
    const uint32_t* Blp = Bl + (size_t)z * bzw + (size_t)(n0 >> 7) * 16384;
    const float* bp = bias + (size_t)z * biz + n0;

    const int lane = t & 31, w = t >> 5;
    const int wM = w >> 2, wN = w & 3;           // warp grid 2(M) x 4(N)
    const int g = lane >> 2, cl = lane & 3;

    float acc[4][4][4];
#pragma unroll
    for (int i = 0; i < 4; i++)
#pragma unroll
        for (int j = 0; j < 4; j++)
#pragma unroll
            for (int k = 0; k < 4; k++) acc[i][j][k] = 0.f;

    float4 va[4];
    uint4 rbh[2], rbl[2];

    // ---- staging load (gmem -> regs) for k-chunk base kb ----
    auto ldstage = [&](int kb) {
#pragma unroll
        for (int i = 0; i < 4; i++) {
            int idx = t + i * 256, row = idx >> 3, f4 = idx & 7;
            va[i] = *(const float4*)(Ap + (size_t)row * lda + kb + f4 * 4);
            if (SUBR) {
                // sender GEMM: GEMM row (m0+row) IS the batch index
                float4 rv = *(const float4*)(R + ((size_t)(m0 + row) << 8) + kb + f4 * 4);
                va[i].x = rv.x - va[i].x; va[i].y = rv.y - va[i].y;
                va[i].z = rv.z - va[i].z; va[i].w = rv.w - va[i].w;
            }
        }
        const uint32_t* bh = Bhp + (size_t)(kb >> 5) * 2048 + t * 8;
        const uint32_t* bl = Blp + (size_t)(kb >> 5) * 2048 + t * 8;
        rbh[0] = *(const uint4*)bh; rbh[1] = *(const uint4*)(bh + 4);
        rbl[0] = *(const uint4*)bl; rbl[1] = *(const uint4*)(bl + 4);
    };
    // ---- regs -> smem ----
    auto ststage = [&](int p) {
        uint32_t* A0 = smem + (p * 2 + 0) * 2048;
        uint32_t* A1 = smem + (p * 2 + 1) * 2048;
#pragma unroll
        for (int i = 0; i < 4; i++) {
            int idx = t + i * 256, row = idx >> 3, f4 = idx & 7;
            int ks = f4 >> 2, j = f4 & 3;
            int w0 = (2 * ((2 * j) & 3) + ((2 * j) >> 2)) ^ (ks << 1);
            int w1 = (2 * ((2 * j + 1) & 3) + ((2 * j + 1) >> 2)) ^ (ks << 1);
            uint32_t h0, l0, h1, l1;
            int mt = row >> 4, r = row & 15;
            int seg = (mt * 4 + ks * 2 + (r >> 3)) * 64 + (r & 7) * 8;
            split2(va[i].x, va[i].y, h0, l0);
            split2(va[i].z, va[i].w, h1, l1);
            A0[seg + w0] = h0; A1[seg + w0] = l0;
            A0[seg + w1] = h1; A1[seg + w1] = l1;
        }
        uint32_t* B0 = smem + 8192 + (p * 2 + 0) * 2048 + t * 8;
        uint32_t* B1 = smem + 8192 + (p * 2 + 1) * 2048 + t * 8;
        *(uint4*)B0 = rbh[0]; *(uint4*)(B0 + 4) = rbh[1];
        *(uint4*)B1 = rbl[0]; *(uint4*)(B1 + 4) = rbl[1];
    };
    // ---- one k32 chunk: 2 k16 steps of fp16x3 mma ----
    auto compute = [&](int p) {
        const uint32_t* A0 = smem + (p * 2 + 0) * 2048;
        const uint32_t* A1 = smem + (p * 2 + 1) * 2048;
        const uint32_t* B0 = smem + 8192 + (p * 2 + 0) * 2048;
        const uint32_t* B1 = smem + 8192 + (p * 2 + 1) * 2048;
#pragma unroll
        for (int ks = 0; ks < 2; ks++) {
            const int cx = (cl * 2) ^ (ks << 1);
            uint32_t a0[4][4], a1[4][4], b0[4][2], b1[4][2];
#pragma unroll
            for (int mt = 0; mt < 4; mt++) {
                int mtg = wM * 4 + mt;
                int off = (mtg * 4 + ks * 2) * 64 + g * 8 + cx;
                uint2 lo0 = *(const uint2*)(A0 + off);
                uint2 hi0 = *(const uint2*)(A0 + off + 64);
                a0[mt][0] = lo0.x; a0[mt][2] = lo0.y;
                a0[mt][1] = hi0.x; a0[mt][3] = hi0.y;
                uint2 lo1 = *(const uint2*)(A1 + off);
                uint2 hi1 = *(const uint2*)(A1 + off + 64);
                a1[mt][0] = lo1.x; a1[mt][2] = lo1.y;
                a1[mt][1] = hi1.x; a1[mt][3] = hi1.y;
            }
#pragma unroll
            for (int nt = 0; nt < 4; nt++) {
                int ntg = wN * 4 + nt;
                int off = (ntg * 2 + ks) * 64 + g * 8 + cx;
                uint2 v0 = *(const uint2*)(B0 + off);
                b0[nt][0] = v0.x; b0[nt][1] = v0.y;
                uint2 v1 = *(const uint2*)(B1 + off);
                b1[nt][0] = v1.x; b1[nt][1] = v1.y;
            }
#pragma unroll
            for (int mt = 0; mt < 4; mt++)
#pragma unroll
                for (int nt = 0; nt < 4; nt++) {
                    mma16(acc[mt][nt], a0[mt], b0[nt]);   // hi*hi
                    mma16(acc[mt][nt], a0[mt], b1[nt]);   // hi*lo
                    mma16(acc[mt][nt], a1[mt], b0[nt]);   // lo*hi
                }
        }
    };

    // ---- mainloop: 8 chunks, double buffered ----
    ldstage(0);
    ststage(0);
    __syncthreads();
    int p = 0;
    for (int ch = 0; ch < 8; ch++) {
        if (ch < 7) ldstage((ch + 1) * 32);
        compute(p);
        if (ch < 7) {
            ststage(p ^ 1);
            __syncthreads();
            p ^= 1;
        }
    }

    // ---- epilogue: bias + act ----
    const int wm = wM * 64, wn = wN * 32;
#pragma unroll
    for (int mt = 0; mt < 4; mt++) {
        int r0 = wm + mt * 16 + g;
#pragma unroll
        for (int nt = 0; nt < 4; nt++) {
            int col = wn + nt * 8 + (cl << 1);
            float2 b2 = *(const float2*)(bp + col);
            float2 o0, o1;
            o0.x = act<EPI>(acc[mt][nt][0] + b2.x);
            o0.y = act<EPI>(acc[mt][nt][1] + b2.y);
            o1.x = act<EPI>(acc[mt][nt][2] + b2.x);
            o1.y = act<EPI>(acc[mt][nt][3] + b2.y);
            if (OUTH) {
                __half* Ch = (__half*)Cv + (size_t)z * cz + (size_t)m0 * ldc + n0;
                *(__half2*)(Ch + (size_t)r0 * ldc + col)       = __floats2half2_rn(o0.x, o0.y);
                *(__half2*)(Ch + (size_t)(r0 + 8) * ldc + col) = __floats2half2_rn(o1.x, o1.y);
            } else {
                float* Cf = (float*)Cv + (size_t)z * cz + (size_t)m0 * ldc + n0;
                *(float2*)(Cf + (size_t)r0 * ldc + col) = o0;
                *(float2*)(Cf + (size_t)(r0 + 8) * ldc + col) = o1;
            }
        }
    }
}

// ------------------------- attention scores -------------------------
__global__ void __launch_bounds__(256) scores_k(
    const float* __restrict__ Q, const float* __restrict__ Kt)
{
    __shared__ float Ks[32][257];
    int b = blockIdx.x;
    int t = threadIdx.x;
    for (int idx = t; idx < S * H; idx += 256) {
        int k = idx >> 8, c = idx & 255;
        Ks[k][c] = Kt[(size_t)(b * S + k) * H + c];
    }
    __syncthreads();
    int lane = t & 31, w = t >> 5;
#pragma unroll
    for (int qi = 0; qi < 4; qi++) {
        int q = w + qi * 8;
        const float* qrow = Q + (size_t)(b * S + q) * H;
#pragma unroll
        for (int h = 0; h < NH; h++) {
            float accv = 0.f;
#pragma unroll 16
            for (int d = 0; d < HD; d++)
                accv = fmaf(__ldg(qrow + h * HD + d), Ks[lane][h * HD + d], accv);
            g_scores[(size_t)(h * NB + b) * (S * S) + q * S + lane] = accv * 0.125f;
        }
    }
}

// ------------------------- softmax over axis 0 (length 16384) per (q,k) -------------------------
__global__ void __launch_bounds__(256) smax_part_k()
{
    int chunk = blockIdx.x, q = blockIdx.y;
    int t = threadIdx.x, k = t & 31, g = t >> 5;
    float m = -1e30f, sv = 0.f;
    int base = chunk * 512 + g;
    for (int i = 0; i < 64; i++) {
        int bh = base + i * 8;
        float v = g_scores[(size_t)bh * 1024 + q * 32 + k];
        if (v > m) { sv = sv * expf(m - v) + 1.f; m = v; }
        else       { sv += expf(v - m); }
    }
    __shared__ float sm[8][32], ss[8][32];
    sm[g][k] = m; ss[g][k] = sv;
    __syncthreads();
    if (t < 32) {
        float M = sm[0][k];
#pragma unroll
        for (int j = 1; j < 8; j++) M = fmaxf(M, sm[j][k]);
        float Sv = 0.f;
#pragma unroll
        for (int j = 0; j < 8; j++) Sv += ss[j][k] * expf(sm[j][k] - M);
        g_pmax[chunk * 1024 + q * 32 + k] = M;
        g_psum[chunk * 1024 + q * 32 + k] = Sv;
    }
}

__global__ void smax_final_k()
{
    int t = threadIdx.x;
    float M = -1e30f;
    for (int c = 0; c < 32; c++) M = fmaxf(M, g_pmax[c * 1024 + t]);
    float Sv = 0.f;
    for (int c = 0; c < 32; c++) Sv += g_psum[c * 1024 + t] * expf(g_pmax[c * 1024 + t] - M);
    g_smax[t] = M;
    g_ssum[t] = Sv;
}

// ------------------------- weighted-V + Vr + relu + InstanceNorm (fused) -------------------------
__global__ void __launch_bounds__(256) attnout_k(
    const float* __restrict__ V, const float* __restrict__ Vr,
    const float* __restrict__ gamma, const float* __restrict__ beta,
    float* __restrict__ out)
{
    __shared__ float Vsm[32][256];
    __shared__ float wsm[4][32];
    __shared__ float s_stat[2];
    __shared__ float red[2][8];
    __shared__ float s_smax[1024], s_rs[1024];
    int b = blockIdx.x;
    int t = threadIdx.x;
    for (int idx = t; idx < 32 * 256; idx += 256)
        Vsm[idx >> 8][idx & 255] = V[(size_t)(b * 32) * 256 + idx];
    for (int idx = t; idx < 1024; idx += 256) {
        s_smax[idx] = g_smax[idx];
        s_rs[idx]   = 1.f / g_ssum[idx];
    }
    float gam = gamma[t], bet = beta[t];
    int lane = t & 31, wid = t >> 5;
    int hh = t >> 6;
    __syncthreads();
    for (int q = 0; q < 32; q++) {
        if (t < 128) {
            int h = t >> 5, k = t & 31;
            float svv = g_scores[(size_t)(h * NB + b) * 1024 + q * 32 + k];
            wsm[h][k] = expf(svv - s_smax[q * 32 + k]) * s_rs[q * 32 + k];
        }
        __syncthreads();
        float accv = 0.f;
#pragma unroll 8
        for (int k = 0; k < 32; k++)
            accv = fmaf(wsm[hh][k], Vsm[k][t], accv);
        float o = fmaxf(accv + Vr[(size_t)(b * 32 + q) * 256 + t], 0.f);
        float v1 = o, v2 = o * o;
#pragma unroll
        for (int off = 16; off; off >>= 1) {
            v1 += __shfl_down_sync(0xffffffffu, v1, off);
            v2 += __shfl_down_sync(0xffffffffu, v2, off);
        }
        if (lane == 0) { red[0][wid] = v1; red[1][wid] = v2; }
        __syncthreads();
        if (t == 0) {
            float s1 = 0.f, s2 = 0.f;
#pragma unroll
            for (int i = 0; i < 8; i++) { s1 += red[0][i]; s2 += red[1][i]; }
            float mu  = s1 * (1.f / 256.f);
            float var = s2 * (1.f / 256.f) - mu * mu;
            s_stat[0] = mu;
            s_stat[1] = rsqrtf(var + 1e-5f);
        }
        __syncthreads();
        out[(size_t)(b * 32 + q) * 256 + t] = gam * ((o - s_stat[0]) * s_stat[1]) + bet;
        __syncthreads();
    }
}

// ------------------------- GNN helpers -------------------------
__global__ void rowsum_k(const float* __restrict__ X, float* __restrict__ R)
{
    int idx = blockIdx.x * 256 + threadIdx.x;  // NB*H
    int b = idx >> 8, h = idx & 255;
    float accv = 0.f;
#pragma unroll
    for (int s = 0; s < 32; s++)
        accv += X[(size_t)((b << 5) + s) * 256 + h];
    R[idx] = accv;
    (void)h;
}

__global__ void gru_k(const float* __restrict__ xin, float* __restrict__ xout)
{
    size_t idx = (size_t)blockIdx.x * 256 + threadIdx.x;
    int row = (int)(idx >> 8), c = (int)(idx & 255);
    size_t base = (size_t)row * 768 + c;
    float ir = __half2float(g_gi[base]);
    float iz = __half2float(g_gi[base + 256]);
    float inn = __half2float(g_gi[base + 512]);
    float hr = __half2float(g_gh[base]);
    float hz = __half2float(g_gh[base + 256]);
    float hn = __half2float(g_gh[base + 512]);
    float r = 1.f / (1.f + expf(-(ir + hr)));
    float z = 1.f / (1.f + expf(-(iz + hz)));
    float n = tanhf(inn + r * hn);
    float x = xin[idx];
    xout[idx] = x + (1.f - z) * n + z * x;
}

// ------------------------- final credit head -------------------------
__global__ void __launch_bounds__(256) cred_k(
    const float* __restrict__ M1, const float* __restrict__ M2,
    float* __restrict__ out)
{
    int wid = threadIdx.x >> 5, lane = threadIdx.x & 31;
    int row = blockIdx.x * 8 + wid;
    const float* p1 = M1 + (size_t)row * 256;
    const float* p2 = M2 + (size_t)row * 256;
    float accv = 0.f;
#pragma unroll
    for (int j = 0; j < 8; j++)
        accv = fmaf(p1[lane + j * 32], p2[lane + j * 32], accv);
#pragma unroll
    for (int off = 16; off; off >>= 1)
        accv += __shfl_down_sync(0xffffffffu, accv, off);
    if (lane == 0) out[row] = 1.f / (1.f + expf(-accv));
}

// ------------------------- host orchestration -------------------------
#define SMEM_MM 65536

extern "C" void kernel_launch(void* const* d_in, const int* in_sizes, int n_in,
                              void* d_out, int out_size)
{
    (void)in_sizes; (void)n_in; (void)out_size;
    const float* inputs  = (const float*)d_in[0];
    const float* embed_w = (const float*)d_in[1];
    const float* embed_b = (const float*)d_in[2];
    const float* wq  = (const float*)d_in[3];
    const float* bq  = (const float*)d_in[4];
    const float* wk  = (const float*)d_in[5];
    const float* bk  = (const float*)d_in[6];
    const float* wv  = (const float*)d_in[7];
    const float* bv  = (const float*)d_in[8];
    const float* wvr = (const float*)d_in[9];
    const float* bvr = (const float*)d_in[10];
    const float* gamma = (const float*)d_in[11];
    const float* beta  = (const float*)d_in[12];
    const float* mp_w1 = (const float*)d_in[13];
    const float* mp_b1 = (const float*)d_in[14];
    const float* mp_w3 = (const float*)d_in[15];
    const float* mp_b3 = (const float*)d_in[16];
    const float* gru_wih = (const float*)d_in[17];
    const float* gru_whh = (const float*)d_in[18];
    const float* gru_bih = (const float*)d_in[19];
    const float* gru_bhh = (const float*)d_in[20];
    const float* mlp1_w = (const float*)d_in[21];
    const float* mlp1_b = (const float*)d_in[22];
    const float* mlp2_w = (const float*)d_in[23];
    const float* mlp2_b = (const float*)d_in[24];

    float *feat, *qb, *kb, *vb, *vrb, *attn, *xa, *xb, *rowsum;
    uint32_t *wbh, *wbl;
    cudaGetSymbolAddress((void**)&feat,   g_feat);
    cudaGetSymbolAddress((void**)&qb,     g_q);
    cudaGetSymbolAddress((void**)&kb,     g_k);
    cudaGetSymbolAddress((void**)&vb,     g_v);
    cudaGetSymbolAddress((void**)&vrb,    g_vr);
    cudaGetSymbolAddress((void**)&attn,   g_attn);
    cudaGetSymbolAddress((void**)&xa,     g_xa);
    cudaGetSymbolAddress((void**)&xb,     g_xb);
    cudaGetSymbolAddress((void**)&rowsum, g_rowsum);
    cudaGetSymbolAddress((void**)&wbh,    g_wbh);
    cudaGetSymbolAddress((void**)&wbl,    g_wbl);
    __half *gi, *gh;
    cudaGetSymbolAddress((void**)&gi, g_gi);
    cudaGetSymbolAddress((void**)&gh, g_gh);

    cudaFuncSetAttribute(mm_k<0, false, false>, cudaFuncAttributeMaxDynamicSharedMemorySize, SMEM_MM);
    cudaFuncSetAttribute(mm_k<0, false, true >, cudaFuncAttributeMaxDynamicSharedMemorySize, SMEM_MM);
    cudaFuncSetAttribute(mm_k<0, true,  false>, cudaFuncAttributeMaxDynamicSharedMemorySize, SMEM_MM);
    cudaFuncSetAttribute(mm_k<1, false, false>, cudaFuncAttributeMaxDynamicSharedMemorySize, SMEM_MM);
    cudaFuncSetAttribute(mm_k<2, false, false>, cudaFuncAttributeMaxDynamicSharedMemorySize, SMEM_MM);
    cudaFuncSetAttribute(mm_k<3, false, false>, cudaFuncAttributeMaxDynamicSharedMemorySize, SMEM_MM);

    float* out_cred = (float*)d_out;
    float* out_fs   = (float*)d_out + BS;   // fs written in place

    // ---- one-time-per-replay weight prep (fp32 -> swizzled fp16 hi/lo) ----
    wprep_k<<<dim3(8, 2, 1),  256>>>(embed_w, wbh + W7_OFF + 0 * 32768, wbl + W7_OFF + 0 * 32768, 256, 1);
    wprep_k<<<dim3(8, 2, 1),  256>>>(wq,      wbh + W7_OFF + 1 * 32768, wbl + W7_OFF + 1 * 32768, 256, 1);
    wprep_k<<<dim3(8, 2, 1),  256>>>(wk,      wbh + W7_OFF + 2 * 32768, wbl + W7_OFF + 2 * 32768, 256, 1);
    wprep_k<<<dim3(8, 2, 1),  256>>>(wv,      wbh + W7_OFF + 3 * 32768, wbl + W7_OFF + 3 * 32768, 256, 1);
    wprep_k<<<dim3(8, 2, 1),  256>>>(wvr,     wbh + W7_OFF + 4 * 32768, wbl + W7_OFF + 4 * 32768, 256, 1);
    wprep_k<<<dim3(8, 2, 1),  256>>>(mlp1_w,  wbh + W7_OFF + 5 * 32768, wbl + W7_OFF + 5 * 32768, 256, 1);
    wprep_k<<<dim3(8, 2, 1),  256>>>(mlp2_w,  wbh + W7_OFF + 6 * 32768, wbl + W7_OFF + 6 * 32768, 256, 1);
    wprep_k<<<dim3(8, 2, 32), 256>>>(mp_w1,   wbh + W1_OFF,  wbl + W1_OFF,  256, 1);
    wprep_k<<<dim3(8, 2, 32), 256>>>(mp_w3,   wbh + W3_OFF,  wbl + W3_OFF,  256, 1);
    wprep_k<<<dim3(8, 6, 1),  256>>>(gru_wih, wbh + WIH_OFF, wbl + WIH_OFF, 768, 0);
    wprep_k<<<dim3(8, 6, 1),  256>>>(gru_whh, wbh + WHH_OFF, wbl + WHH_OFF, 768, 0);

    dim3 g2(2, 1024);
    // feat = tanh(inputs @ embed_w + b)
    mm_k<2, false, false><<<g2, 256, SMEM_MM>>>(inputs, H, 0, wbh + W7_OFF, wbl + W7_OFF, 0, embed_b, 0, feat, H, 0, nullptr);
    // Q/K/V/Vr = relu(feat @ W + b)
    mm_k<1, false, false><<<g2, 256, SMEM_MM>>>(feat, H, 0, wbh + W7_OFF + 1 * 32768, wbl + W7_OFF + 1 * 32768, 0, bq,  0, qb,  H, 0, nullptr);
    mm_k<1, false, false><<<g2, 256, SMEM_MM>>>(feat, H, 0, wbh + W7_OFF + 2 * 32768, wbl + W7_OFF + 2 * 32768, 0, bk,  0, kb,  H, 0, nullptr);
    mm_k<1, false, false><<<g2, 256, SMEM_MM>>>(feat, H, 0, wbh + W7_OFF + 3 * 32768, wbl + W7_OFF + 3 * 32768, 0, bv,  0, vb,  H, 0, nullptr);
    mm_k<1, false, false><<<g2, 256, SMEM_MM>>>(feat, H, 0, wbh + W7_OFF + 4 * 32768, wbl + W7_OFF + 4 * 32768, 0, bvr, 0, vrb, H, 0, nullptr);
    // attention
    scores_k<<<NB, 256>>>(qb, kb);
    smax_part_k<<<dim3(32, 32), 256>>>();
    smax_final_k<<<1, 1024>>>();
    attnout_k<<<NB, 256>>>(vb, vrb, gamma, beta, attn);

    // GNN x4 (first output = fs, written directly to d_out region)
    const float* xin_seq[4]  = { attn,   out_fs, xa, xb };
    float*       xout_seq[4] = { out_fs, xa,     xb, xa };
    for (int it = 0; it < 4; it++) {
        const float* x_in = xin_seq[it];
        float* x_out = xout_seq[it];
        dim3 gs(2, 32, 32);  // n-tiles, m-tiles(4096/128), sender
        mm_k<0, false, false><<<gs, 256, SMEM_MM>>>(x_in, S * H, H, wbh + W1_OFF, wbl + W1_OFF, 32768, mp_b1, H, qb, S * H, H, nullptr);
        rowsum_k<<<(NB * H) / 256, 256>>>(qb, rowsum);
        // s3 = (rowsum - s1) @ w3 + b3, fused A-side subtract
        mm_k<0, false, true ><<<gs, 256, SMEM_MM>>>(qb, S * H, H, wbh + W3_OFF, wbl + W3_OFF, 32768, mp_b3, H, kb, S * H, H, rowsum);
        mm_k<0, true,  false><<<dim3(6, 1024), 256, SMEM_MM>>>(kb,   H, 0, wbh + WIH_OFF, wbl + WIH_OFF, 0, gru_bih, 0, gi, 768, 0, nullptr);
        mm_k<0, true,  false><<<dim3(6, 1024), 256, SMEM_MM>>>(x_in, H, 0, wbh + WHH_OFF, wbl + WHH_OFF, 0, gru_bhh, 0, gh, 768, 0, nullptr);
        gru_k<<<(BS * H) / 256, 256>>>(x_in, x_out);
    }

    // head: m1 = tanh(fs3@mlp1), m2 = leaky(fs3@mlp2), cred = sigmoid(sum(m1*m2))
    mm_k<2, false, false><<<g2, 256, SMEM_MM>>>(xa, H, 0, wbh + W7_OFF + 5 * 32768, wbl + W7_OFF + 5 * 32768, 0, mlp1_b, 0, qb, H, 0, nullptr);
    mm_k<3, false, false><<<g2, 256, SMEM_MM>>>(xa, H, 0, wbh + W7_OFF + 6 * 32768, wbl + W7_OFF + 6 * 32768, 0, mlp2_b, 0, kb, H, 0, nullptr);
    cred_k<<<BS / 8, 256>>>(qb, kb, out_cred);
}

// round 15
// speedup vs baseline: 2.0299x; 1.0242x over previous
#include <cuda_runtime.h>
#include <cuda_fp16.h>
#include <cstdint>
#include <math.h>

#define H 256
#define S 32
#define NB 4096            // batch
#define BS (NB * S)        // 131072 flattened rows
#define NH 4
#define HD 64
#define BH (NH * NB)       // 16384 (head*batch axis length)

// ------------------------- scratch (__device__ globals) -------------------------
__device__ float g_feat[BS * H];
__device__ float g_q[BS * H];          // scratch (s1 / m1)
__device__ float g_k[BS * H];          // scratch (s3 / m2)
__device__ float g_qkvr[(size_t)BS * 1024];   // [row][Q|K|V|Vr]
__device__ float g_attn[BS * H];
__device__ float g_xa[BS * H];
__device__ float g_xb[BS * H];
__device__ float g_scores[(size_t)BH * S * S];   // [bh][q][k]
__device__ float g_pmax[32 * S * S];
__device__ float g_psum[32 * S * S];
__device__ float g_smax[S * S];
__device__ float g_ssum[S * S];
__device__ float g_rowsum[NB * H];
__device__ float g_bias4[1024];
__device__ __half g_gi[(size_t)BS * 3 * H];
__device__ __half g_gh[(size_t)BS * 3 * H];

// pre-split, pre-swizzled weights (packed half2 words, hi and lo components)
#define W7_OFF   0u              // 7 matrices, 32768 words each: embed,wq,wk,wv,wvr,mlp1,mlp2
#define W1_OFF   229376u
#define W3_OFF   1277952u
#define WIH_OFF  2326528u
#define WHH_OFF  2424832u
#define WTOT     2523136u
__device__ uint32_t g_wbh[WTOT];
__device__ uint32_t g_wbl[WTOT];

// ------------------------- helpers -------------------------
__device__ __forceinline__ void split2(float x, float y, uint32_t& h, uint32_t& l) {
    __half2 hh = __floats2half2_rn(x, y);
    float2 hf = __half22float2(hh);
    __half2 ll = __floats2half2_rn(x - hf.x, y - hf.y);
    h = *reinterpret_cast<uint32_t*>(&hh);
    l = *reinterpret_cast<uint32_t*>(&ll);
}

__device__ __forceinline__ float fast_sigmoid(float x) {
    return __fdividef(1.f, 1.f + __expf(-x));
}
__device__ __forceinline__ float fast_tanh(float x) {
    return 1.f - __fdividef(2.f, __expf(2.f * x) + 1.f);
}

// D += A@B  (m16n8k16 fp16 in, fp32 accum, row.col)
__device__ __forceinline__ void mma16(float* d, const uint32_t* a, const uint32_t* b) {
    asm volatile("mma.sync.aligned.m16n8k16.row.col.f32.f16.f16.f32 "
        "{%0,%1,%2,%3}, {%4,%5,%6,%7}, {%8,%9}, {%0,%1,%2,%3};"
        : "+f"(d[0]), "+f"(d[1]), "+f"(d[2]), "+f"(d[3])
        : "r"(a[0]), "r"(a[1]), "r"(a[2]), "r"(a[3]), "r"(b[0]), "r"(b[1]));
}

// ------------------------- epilogue activations -------------------------
template <int EPI>
__device__ __forceinline__ float act(float v) {
    if (EPI == 1) return fmaxf(v, 0.f);           // relu
    if (EPI == 2) return fast_tanh(v);            // tanh
    if (EPI == 3) return v > 0.f ? v : 0.01f * v; // leaky relu
    return v;
}

// ------------------------- weight prep: fp32 -> swizzled fp16 hi/lo blocks ----
__global__ void wprep_k(const float* __restrict__ src,
                        uint32_t* __restrict__ dh, uint32_t* __restrict__ dl,
                        int N, int trans)
{
    int z = blockIdx.z, tile = blockIdx.y, c = blockIdx.x;
    const float* Sp = src + (size_t)z * ((size_t)N * 256);
    size_t base = ((size_t)z * (N / 128) + tile) * 16384 + (size_t)c * 2048;
    for (int W = threadIdx.x; W < 2048; W += 256) {
        int nti = W >> 7, ks = (W >> 6) & 1, n8 = (W >> 3) & 7, w = W & 7;
        int wp = w ^ (ks << 1);
        int p = (wp >> 1) | ((wp & 1) << 2);
        int n = tile * 128 + nti * 8 + n8;
        int k0 = c * 32 + ks * 16 + 2 * p;
        float v0, v1;
        if (trans) { v0 = Sp[(size_t)k0 * N + n]; v1 = Sp[(size_t)(k0 + 1) * N + n]; }
        else       { v0 = Sp[(size_t)n * 256 + k0]; v1 = Sp[(size_t)n * 256 + k0 + 1]; }
        uint32_t h, l;
        split2(v0, v1, h, l);
        dh[base + W] = h;
        dl[base + W] = l;
    }
}

__global__ void bias4_k(const float* __restrict__ b0, const float* __restrict__ b1,
                        const float* __restrict__ b2, const float* __restrict__ b3)
{
    int t = blockIdx.x * 256 + threadIdx.x;   // 0..1023
    const float* src = (t < 256) ? b0 : (t < 512) ? b1 : (t < 768) ? b2 : b3;
    g_bias4[t] = src[t & 255];
}

// ------------------------- mma.sync fp16x3 GEMM -------------------------
template <int EPI, bool OUTH, bool SUBR>
__global__ void __launch_bounds__(256) mm_k(
    const float* __restrict__ A, long lda, long az,
    const uint32_t* __restrict__ Bh, const uint32_t* __restrict__ Bl, long bzw,
    const float* __restrict__ bias, long biz,
    void* __restrict__ Cv, long ldc, long cz,
    const float* __restrict__ R)
{
    extern __shared__ uint32_t smem[];
    const int t = threadIdx.x;
    const int m0 = blockIdx.y * 128;
    const int n0 = blockIdx.x * 128;
    const int z  = blockIdx.z;
    const float* Ap = A + (size_t)z * az + (size_t)m0 * lda;
    const uint32_t* Bhp = Bh + (size_t)z * bzw + (size_t)(n0 >> 7) * 16384;
    const uint32_t* Blp = Bl + (size_t)z * bzw + (size_t)(n0 >> 7) * 16384;
    const float* bp = bias + (size_t)z * biz + n0;

    const int lane = t & 31, w = t >> 5;
    const int wM = w >> 2, wN = w & 3;
    const int g = lane >> 2, cl = lane & 3;

    float acc[4][4][4];
#pragma unroll
    for (int i = 0; i < 4; i++)
#pragma unroll
        for (int j = 0; j < 4; j++)
#pragma unroll
            for (int k = 0; k < 4; k++) acc[i][j][k] = 0.f;

    float4 va[4];
    uint4 rbh[2], rbl[2];

    auto ldstage = [&](int kb) {
#pragma unroll
        for (int i = 0; i < 4; i++) {
            int idx = t + i * 256, row = idx >> 3, f4 = idx & 7;
            va[i] = *(const float4*)(Ap + (size_t)row * lda + kb + f4 * 4);
            if (SUBR) {
                float4 rv = *(const float4*)(R + ((size_t)(m0 + row) << 8) + kb + f4 * 4);
                va[i].x = rv.x - va[i].x; va[i].y = rv.y - va[i].y;
                va[i].z = rv.z - va[i].z; va[i].w = rv.w - va[i].w;
            }
        }
        const uint32_t* bh = Bhp + (size_t)(kb >> 5) * 2048 + t * 8;
        const uint32_t* bl = Blp + (size_t)(kb >> 5) * 2048 + t * 8;
        rbh[0] = *(const uint4*)bh; rbh[1] = *(const uint4*)(bh + 4);
        rbl[0] = *(const uint4*)bl; rbl[1] = *(const uint4*)(bl + 4);
    };
    auto ststage = [&](int p) {
        uint32_t* A0 = smem + (p * 2 + 0) * 2048;
        uint32_t* A1 = smem + (p * 2 + 1) * 2048;
#pragma unroll
        for (int i = 0; i < 4; i++) {
            int idx = t + i * 256, row = idx >> 3, f4 = idx & 7;
            int ks = f4 >> 2, j = f4 & 3;
            int w0 = (2 * ((2 * j) & 3) + ((2 * j) >> 2)) ^ (ks << 1);
            int w1 = (2 * ((2 * j + 1) & 3) + ((2 * j + 1) >> 2)) ^ (ks << 1);
            uint32_t h0, l0, h1, l1;
            int mt = row >> 4, r = row & 15;
            int seg = (mt * 4 + ks * 2 + (r >> 3)) * 64 + (r & 7) * 8;
            split2(va[i].x, va[i].y, h0, l0);
            split2(va[i].z, va[i].w, h1, l1);
            A0[seg + w0] = h0; A1[seg + w0] = l0;
            A0[seg + w1] = h1; A1[seg + w1] = l1;
        }
        uint32_t* B0 = smem + 8192 + (p * 2 + 0) * 2048 + t * 8;
        uint32_t* B1 = smem + 8192 + (p * 2 + 1) * 2048 + t * 8;
        *(uint4*)B0 = rbh[0]; *(uint4*)(B0 + 4) = rbh[1];
        *(uint4*)B1 = rbl[0]; *(uint4*)(B1 + 4) = rbl[1];
    };
    auto compute = [&](int p) {
        const uint32_t* A0 = smem + (p * 2 + 0) * 2048;
        const uint32_t* A1 = smem + (p * 2 + 1) * 2048;
        const uint32_t* B0 = smem + 8192 + (p * 2 + 0) * 2048;
        const uint32_t* B1 = smem + 8192 + (p * 2 + 1) * 2048;
#pragma unroll
        for (int ks = 0; ks < 2; ks++) {
            const int cx = (cl * 2) ^ (ks << 1);
            uint32_t a0[4][4], a1[4][4], b0[4][2], b1[4][2];
#pragma unroll
            for (int mt = 0; mt < 4; mt++) {
                int mtg = wM * 4 + mt;
                int off = (mtg * 4 + ks * 2) * 64 + g * 8 + cx;
                uint2 lo0 = *(const uint2*)(A0 + off);
                uint2 hi0 = *(const uint2*)(A0 + off + 64);
                a0[mt][0] = lo0.x; a0[mt][2] = lo0.y;
                a0[mt][1] = hi0.x; a0[mt][3] = hi0.y;
                uint2 lo1 = *(const uint2*)(A1 + off);
                uint2 hi1 = *(const uint2*)(A1 + off + 64);
                a1[mt][0] = lo1.x; a1[mt][2] = lo1.y;
                a1[mt][1] = hi1.x; a1[mt][3] = hi1.y;
            }
#pragma unroll
            for (int nt = 0; nt < 4; nt++) {
                int ntg = wN * 4 + nt;
                int off = (ntg * 2 + ks) * 64 + g * 8 + cx;
                uint2 v0 = *(const uint2*)(B0 + off);
                b0[nt][0] = v0.x; b0[nt][1] = v0.y;
                uint2 v1 = *(const uint2*)(B1 + off);
                b1[nt][0] = v1.x; b1[nt][1] = v1.y;
            }
#pragma unroll
            for (int mt = 0; mt < 4; mt++)
#pragma unroll
                for (int nt = 0; nt < 4; nt++) {
                    mma16(acc[mt][nt], a0[mt], b0[nt]);   // hi*hi
                    mma16(acc[mt][nt], a0[mt], b1[nt]);   // hi*lo
                    mma16(acc[mt][nt], a1[mt], b0[nt]);   // lo*hi
                }
        }
    };

    ldstage(0);
    ststage(0);
    __syncthreads();
    int p = 0;
    for (int ch = 0; ch < 8; ch++) {
        if (ch < 7) ldstage((ch + 1) * 32);
        compute(p);
        if (ch < 7) {
            ststage(p ^ 1);
            __syncthreads();
            p ^= 1;
        }
    }

    const int wm = wM * 64, wn = wN * 32;
#pragma unroll
    for (int mt = 0; mt < 4; mt++) {
        int r0 = wm + mt * 16 + g;
#pragma unroll
        for (int nt = 0; nt < 4; nt++) {
            int col = wn + nt * 8 + (cl << 1);
            float2 b2 = *(const float2*)(bp + col);
            float2 o0, o1;
            o0.x = act<EPI>(acc[mt][nt][0] + b2.x);
            o0.y = act<EPI>(acc[mt][nt][1] + b2.y);
            o1.x = act<EPI>(acc[mt][nt][2] + b2.x);
            o1.y = act<EPI>(acc[mt][nt][3] + b2.y);
            if (OUTH) {
                __half* Ch = (__half*)Cv + (size_t)z * cz + (size_t)m0 * ldc + n0;
                *(__half2*)(Ch + (size_t)r0 * ldc + col)       = __floats2half2_rn(o0.x, o0.y);
                *(__half2*)(Ch + (size_t)(r0 + 8) * ldc + col) = __floats2half2_rn(o1.x, o1.y);
            } else {
                float* Cf = (float*)Cv + (size_t)z * cz + (size_t)m0 * ldc + n0;
                *(float2*)(Cf + (size_t)r0 * ldc + col) = o0;
                *(float2*)(Cf + (size_t)(r0 + 8) * ldc + col) = o1;
            }
        }
    }
}

// ------------------------- attention scores -------------------------
// QKVR layout: [row][0:256 Q | 256:512 K | 512:768 V | 768:1024 Vr]
__global__ void __launch_bounds__(256) scores_k(const float* __restrict__ QK)
{
    __shared__ float Ks[32][257];
    int b = blockIdx.x;
    int t = threadIdx.x;
    for (int idx = t; idx < S * H; idx += 256) {
        int k = idx >> 8, c = idx & 255;
        Ks[k][c] = QK[(size_t)(b * S + k) * 1024 + 256 + c];
    }
    __syncthreads();
    int lane = t & 31, w = t >> 5;
#pragma unroll
    for (int qi = 0; qi < 4; qi++) {
        int q = w + qi * 8;
        const float* qrow = QK + (size_t)(b * S + q) * 1024;
#pragma unroll
        for (int h = 0; h < NH; h++) {
            float accv = 0.f;
#pragma unroll 16
            for (int d = 0; d < HD; d++)
                accv = fmaf(__ldg(qrow + h * HD + d), Ks[lane][h * HD + d], accv);
            g_scores[(size_t)(h * NB + b) * (S * S) + q * S + lane] = accv * 0.125f;
        }
    }
}

// ------------------------- softmax over axis 0 (length 16384) per (q,k) -------------------------
__global__ void __launch_bounds__(256) smax_part_k()
{
    int chunk = blockIdx.x, q = blockIdx.y;
    int t = threadIdx.x, k = t & 31, g = t >> 5;
    float m = -1e30f, sv = 0.f;
    int base = chunk * 512 + g;
    for (int i = 0; i < 64; i++) {
        int bh = base + i * 8;
        float v = g_scores[(size_t)bh * 1024 + q * 32 + k];
        if (v > m) { sv = sv * __expf(m - v) + 1.f; m = v; }
        else       { sv += __expf(v - m); }
    }
    __shared__ float sm[8][32], ss[8][32];
    sm[g][k] = m; ss[g][k] = sv;
    __syncthreads();
    if (t < 32) {
        float M = sm[0][k];
#pragma unroll
        for (int j = 1; j < 8; j++) M = fmaxf(M, sm[j][k]);
        float Sv = 0.f;
#pragma unroll
        for (int j = 0; j < 8; j++) Sv += ss[j][k] * __expf(sm[j][k] - M);
        g_pmax[chunk * 1024 + q * 32 + k] = M;
        g_psum[chunk * 1024 + q * 32 + k] = Sv;
    }
}

__global__ void smax_final_k()
{
    int t = threadIdx.x;
    float M = -1e30f;
    for (int c = 0; c < 32; c++) M = fmaxf(M, g_pmax[c * 1024 + t]);
    float Sv = 0.f;
    for (int c = 0; c < 32; c++) Sv += g_psum[c * 1024 + t] * __expf(g_pmax[c * 1024 + t] - M);
    g_smax[t] = M;
    g_ssum[t] = Sv;
}

// ------------------------- weighted-V + Vr + relu + InstanceNorm (fused) -------------------------
__global__ void __launch_bounds__(256) attnout_k(
    const float* __restrict__ QKVR,
    const float* __restrict__ gamma, const float* __restrict__ beta,
    float* __restrict__ out)
{
    __shared__ float Vsm[32][256];
    __shared__ float wsm[4][32];
    __shared__ float s_stat[2];
    __shared__ float red[2][8];
    __shared__ float s_smax[1024], s_rs[1024];
    int b = blockIdx.x;
    int t = threadIdx.x;
    for (int idx = t; idx < 32 * 256; idx += 256) {
        int row = idx >> 8, c = idx & 255;
        Vsm[row][c] = QKVR[(size_t)(b * 32 + row) * 1024 + 512 + c];
    }
    for (int idx = t; idx < 1024; idx += 256) {
        s_smax[idx] = g_smax[idx];
        s_rs[idx]   = __fdividef(1.f, g_ssum[idx]);
    }
    float gam = gamma[t], bet = beta[t];
    int lane = t & 31, wid = t >> 5;
    int hh = t >> 6;
    __syncthreads();
    for (int q = 0; q < 32; q++) {
        if (t < 128) {
            int h = t >> 5, k = t & 31;
            float svv = g_scores[(size_t)(h * NB + b) * 1024 + q * 32 + k];
            wsm[h][k] = __expf(svv - s_smax[q * 32 + k]) * s_rs[q * 32 + k];
        }
        __syncthreads();
        float accv = 0.f;
#pragma unroll 8
        for (int k = 0; k < 32; k++)
            accv = fmaf(wsm[hh][k], Vsm[k][t], accv);
        float o = fmaxf(accv + QKVR[(size_t)(b * 32 + q) * 1024 + 768 + t], 0.f);
        float v1 = o, v2 = o * o;
#pragma unroll
        for (int off = 16; off; off >>= 1) {
            v1 += __shfl_down_sync(0xffffffffu, v1, off);
            v2 += __shfl_down_sync(0xffffffffu, v2, off);
        }
        if (lane == 0) { red[0][wid] = v1; red[1][wid] = v2; }
        __syncthreads();
        if (t == 0) {
            float s1 = 0.f, s2 = 0.f;
#pragma unroll
            for (int i = 0; i < 8; i++) { s1 += red[0][i]; s2 += red[1][i]; }
            float mu  = s1 * (1.f / 256.f);
            float var = s2 * (1.f / 256.f) - mu * mu;
            s_stat[0] = mu;
            s_stat[1] = rsqrtf(var + 1e-5f);
        }
        __syncthreads();
        out[(size_t)(b * 32 + q) * 256 + t] = gam * ((o - s_stat[0]) * s_stat[1]) + bet;
        __syncthreads();
    }
}

// ------------------------- GNN helpers -------------------------
__global__ void rowsum_k(const float* __restrict__ X, float* __restrict__ R)
{
    int idx = blockIdx.x * 256 + threadIdx.x;  // NB*H
    int b = idx >> 8, h = idx & 255;
    float accv = 0.f;
#pragma unroll
    for (int s = 0; s < 32; s++)
        accv += X[(size_t)((b << 5) + s) * 256 + h];
    R[idx] = accv;
    (void)h;
}

__global__ void gru_k(const float* __restrict__ xin, float* __restrict__ xout)
{
    size_t idx = (size_t)blockIdx.x * 256 + threadIdx.x;
    int row = (int)(idx >> 8), c = (int)(idx & 255);
    size_t base = (size_t)row * 768 + c;
    float ir = __half2float(g_gi[base]);
    float iz = __half2float(g_gi[base + 256]);
    float inn = __half2float(g_gi[base + 512]);
    float hr = __half2float(g_gh[base]);
    float hz = __half2float(g_gh[base + 256]);
    float hn = __half2float(g_gh[base + 512]);
    float r = fast_sigmoid(ir + hr);
    float z = fast_sigmoid(iz + hz);
    float n = fast_tanh(inn + r * hn);
    float x = xin[idx];
    xout[idx] = x + (1.f - z) * n + z * x;
}

// ------------------------- final credit head -------------------------
__global__ void __launch_bounds__(256) cred_k(
    const float* __restrict__ M1, const float* __restrict__ M2,
    float* __restrict__ out)
{
    int wid = threadIdx.x >> 5, lane = threadIdx.x & 31;
    int row = blockIdx.x * 8 + wid;
    const float* p1 = M1 + (size_t)row * 256;
    const float* p2 = M2 + (size_t)row * 256;
    float accv = 0.f;
#pragma unroll
    for (int j = 0; j < 8; j++)
        accv = fmaf(p1[lane + j * 32], p2[lane + j * 32], accv);
#pragma unroll
    for (int off = 16; off; off >>= 1)
        accv += __shfl_down_sync(0xffffffffu, accv, off);
    if (lane == 0) out[row] = fast_sigmoid(accv);
}

// ------------------------- host orchestration -------------------------
#define SMEM_MM 65536

extern "C" void kernel_launch(void* const* d_in, const int* in_sizes, int n_in,
                              void* d_out, int out_size)
{
    (void)in_sizes; (void)n_in; (void)out_size;
    const float* inputs  = (const float*)d_in[0];
    const float* embed_w = (const float*)d_in[1];
    const float* embed_b = (const float*)d_in[2];
    const float* wq  = (const float*)d_in[3];
    const float* bq  = (const float*)d_in[4];
    const float* wk  = (const float*)d_in[5];
    const float* bk  = (const float*)d_in[6];
    const float* wv  = (const float*)d_in[7];
    const float* bv  = (const float*)d_in[8];
    const float* wvr = (const float*)d_in[9];
    const float* bvr = (const float*)d_in[10];
    const float* gamma = (const float*)d_in[11];
    const float* beta  = (const float*)d_in[12];
    const float* mp_w1 = (const float*)d_in[13];
    const float* mp_b1 = (const float*)d_in[14];
    const float* mp_w3 = (const float*)d_in[15];
    const float* mp_b3 = (const float*)d_in[16];
    const float* gru_wih = (const float*)d_in[17];
    const float* gru_whh = (const float*)d_in[18];
    const float* gru_bih = (const float*)d_in[19];
    const float* gru_bhh = (const float*)d_in[20];
    const float* mlp1_w = (const float*)d_in[21];
    const float* mlp1_b = (const float*)d_in[22];
    const float* mlp2_w = (const float*)d_in[23];
    const float* mlp2_b = (const float*)d_in[24];

    float *feat, *qb, *kb, *qkvr, *attn, *xa, *xb, *rowsum, *bias4;
    uint32_t *wbh, *wbl;
    cudaGetSymbolAddress((void**)&feat,   g_feat);
    cudaGetSymbolAddress((void**)&qb,     g_q);
    cudaGetSymbolAddress((void**)&kb,     g_k);
    cudaGetSymbolAddress((void**)&qkvr,   g_qkvr);
    cudaGetSymbolAddress((void**)&attn,   g_attn);
    cudaGetSymbolAddress((void**)&xa,     g_xa);
    cudaGetSymbolAddress((void**)&xb,     g_xb);
    cudaGetSymbolAddress((void**)&rowsum, g_rowsum);
    cudaGetSymbolAddress((void**)&bias4,  g_bias4);
    cudaGetSymbolAddress((void**)&wbh,    g_wbh);
    cudaGetSymbolAddress((void**)&wbl,    g_wbl);
    __half *gi, *gh;
    cudaGetSymbolAddress((void**)&gi, g_gi);
    cudaGetSymbolAddress((void**)&gh, g_gh);

    cudaFuncSetAttribute(mm_k<0, false, false>, cudaFuncAttributeMaxDynamicSharedMemorySize, SMEM_MM);
    cudaFuncSetAttribute(mm_k<0, false, true >, cudaFuncAttributeMaxDynamicSharedMemorySize, SMEM_MM);
    cudaFuncSetAttribute(mm_k<0, true,  false>, cudaFuncAttributeMaxDynamicSharedMemorySize, SMEM_MM);
    cudaFuncSetAttribute(mm_k<1, false, false>, cudaFuncAttributeMaxDynamicSharedMemorySize, SMEM_MM);
    cudaFuncSetAttribute(mm_k<2, false, false>, cudaFuncAttributeMaxDynamicSharedMemorySize, SMEM_MM);
    cudaFuncSetAttribute(mm_k<3, false, false>, cudaFuncAttributeMaxDynamicSharedMemorySize, SMEM_MM);

    float* out_cred = (float*)d_out;
    float* out_fs   = (float*)d_out + BS;   // fs written in place

    // ---- one-time-per-replay weight prep (fp32 -> swizzled fp16 hi/lo) ----
    wprep_k<<<dim3(8, 2, 1),  256>>>(embed_w, wbh + W7_OFF + 0 * 32768, wbl + W7_OFF + 0 * 32768, 256, 1);
    wprep_k<<<dim3(8, 2, 1),  256>>>(wq,      wbh + W7_OFF + 1 * 32768, wbl + W7_OFF + 1 * 32768, 256, 1);
    wprep_k<<<dim3(8, 2, 1),  256>>>(wk,      wbh + W7_OFF + 2 * 32768, wbl + W7_OFF + 2 * 32768, 256, 1);
    wprep_k<<<dim3(8, 2, 1),  256>>>(wv,      wbh + W7_OFF + 3 * 32768, wbl + W7_OFF + 3 * 32768, 256, 1);
    wprep_k<<<dim3(8, 2, 1),  256>>>(wvr,     wbh + W7_OFF + 4 * 32768, wbl + W7_OFF + 4 * 32768, 256, 1);
    wprep_k<<<dim3(8, 2, 1),  256>>>(mlp1_w,  wbh + W7_OFF + 5 * 32768, wbl + W7_OFF + 5 * 32768, 256, 1);
    wprep_k<<<dim3(8, 2, 1),  256>>>(mlp2_w,  wbh + W7_OFF + 6 * 32768, wbl + W7_OFF + 6 * 32768, 256, 1);
    wprep_k<<<dim3(8, 2, 32), 256>>>(mp_w1,   wbh + W1_OFF,  wbl + W1_OFF,  256, 1);
    wprep_k<<<dim3(8, 2, 32), 256>>>(mp_w3,   wbh + W3_OFF,  wbl + W3_OFF,  256, 1);
    wprep_k<<<dim3(8, 6, 1),  256>>>(gru_wih, wbh + WIH_OFF, wbl + WIH_OFF, 768, 0);
    wprep_k<<<dim3(8, 6, 1),  256>>>(gru_whh, wbh + WHH_OFF, wbl + WHH_OFF, 768, 0);
    bias4_k<<<4, 256>>>(bq, bk, bv, bvr);

    dim3 g2(2, 1024);
    // feat = tanh(inputs @ embed_w + b)
    mm_k<2, false, false><<<g2, 256, SMEM_MM>>>(inputs, H, 0, wbh + W7_OFF, wbl + W7_OFF, 0, embed_b, 0, feat, H, 0, nullptr);
    // [Q|K|V|Vr] = relu(feat @ [wq|wk|wv|wvr] + [b4]) in ONE launch (weights contiguous)
    mm_k<1, false, false><<<dim3(8, 1024), 256, SMEM_MM>>>(feat, H, 0,
        wbh + W7_OFF + 32768, wbl + W7_OFF + 32768, 0, bias4, 0, qkvr, 1024, 0, nullptr);
    // attention
    scores_k<<<NB, 256>>>(qkvr);
    smax_part_k<<<dim3(32, 32), 256>>>();
    smax_final_k<<<1, 1024>>>();
    attnout_k<<<NB, 256>>>(qkvr, gamma, beta, attn);

    // GNN x4 (first output = fs, written directly to d_out region)
    const float* xin_seq[4]  = { attn,   out_fs, xa, xb };
    float*       xout_seq[4] = { out_fs, xa,     xb, xa };
    for (int it = 0; it < 4; it++) {
        const float* x_in = xin_seq[it];
        float* x_out = xout_seq[it];
        dim3 gs(2, 32, 32);  // n-tiles, m-tiles(4096/128), sender
        mm_k<0, false, false><<<gs, 256, SMEM_MM>>>(x_in, S * H, H, wbh + W1_OFF, wbl + W1_OFF, 32768, mp_b1, H, qb, S * H, H, nullptr);
        rowsum_k<<<(NB * H) / 256, 256>>>(qb, rowsum);
        mm_k<0, false, true ><<<gs, 256, SMEM_MM>>>(qb, S * H, H, wbh + W3_OFF, wbl + W3_OFF, 32768, mp_b3, H, kb, S * H, H, rowsum);
        mm_k<0, true,  false><<<dim3(6, 1024), 256, SMEM_MM>>>(kb,   H, 0, wbh + WIH_OFF, wbl + WIH_OFF, 0, gru_bih, 0, gi, 768, 0, nullptr);
        mm_k<0, true,  false><<<dim3(6, 1024), 256, SMEM_MM>>>(x_in, H, 0, wbh + WHH_OFF, wbl + WHH_OFF, 0, gru_bhh, 0, gh, 768, 0, nullptr);
        gru_k<<<(BS * H) / 256, 256>>>(x_in, x_out);
    }

    // head: m1 = tanh(fs3@mlp1), m2 = leaky(fs3@mlp2), cred = sigmoid(sum(m1*m2))
    mm_k<2, false, false><<<g2, 256, SMEM_MM>>>(xa, H, 0, wbh + W7_OFF + 5 * 32768, wbl + W7_OFF + 5 * 32768, 0, mlp1_b, 0, qb, H, 0, nullptr);
    mm_k<3, false, false><<<g2, 256, SMEM_MM>>>(xa, H, 0, wbh + W7_OFF + 6 * 32768, wbl + W7_OFF + 6 * 32768, 0, mlp2_b, 0, kb, H, 0, nullptr);
    cred_k<<<BS / 8, 256>>>(qb, kb, out_cred);
}

// round 17
// speedup vs baseline: 2.0570x; 1.0133x over previous
#include <cuda_runtime.h>
#include <cuda_fp16.h>
#include <cstdint>
#include <math.h>

#define H 256
#define S 32
#define NB 4096            // batch
#define BS (NB * S)        // 131072 flattened rows
#define NH 4
#define HD 64
#define BH (NH * NB)       // 16384 (head*batch axis length)

#define LO_SCALE   2048.0f
#define LO_INV     4.8828125e-4f

// ------------------------- scratch (__device__ globals) -------------------------
__device__ float g_feat[BS * H];
__device__ float g_q[BS * H];          // scratch (s1 / m1)
__device__ float g_k[BS * H];          // scratch (s3 / m2)
__device__ float g_qkvr[(size_t)BS * 1024];   // [row][Q|K|V|Vr]
__device__ float g_attn[BS * H];
__device__ float g_xa[BS * H];
__device__ float g_xb[BS * H];
__device__ float g_scores[(size_t)BH * S * S];   // [bh][q][k]
__device__ float g_pmax[32 * S * S];
__device__ float g_psum[32 * S * S];
__device__ float g_smax[S * S];
__device__ float g_ssum[S * S];
__device__ float g_rowsum[NB * H];
__device__ float g_bias4[1024];
__device__ __half g_gi[(size_t)BS * 3 * H];
__device__ __half g_gh[(size_t)BS * 3 * H];

// pre-split, pre-swizzled weights (packed half2 words, hi and lo components;
// lo is pre-scaled by LO_SCALE)
#define W7_OFF   0u              // 7 matrices, 32768 words each: embed,wq,wk,wv,wvr,mlp1,mlp2
#define W1_OFF   229376u
#define W3_OFF   1277952u
#define WIH_OFF  2326528u
#define WHH_OFF  2424832u
#define WTOT     2523136u
__device__ uint32_t g_wbh[WTOT];
__device__ uint32_t g_wbl[WTOT];

// ------------------------- helpers -------------------------
// split (x,y) into packed fp16 hi + fp16 lo*LO_SCALE (combined ~21-22 mantissa bits)
__device__ __forceinline__ void split2(float x, float y, uint32_t& h, uint32_t& l) {
    __half2 hh = __floats2half2_rn(x, y);
    float2 hf = __half22float2(hh);
    __half2 ll = __floats2half2_rn((x - hf.x) * LO_SCALE, (y - hf.y) * LO_SCALE);
    h = *reinterpret_cast<uint32_t*>(&hh);
    l = *reinterpret_cast<uint32_t*>(&ll);
}

__device__ __forceinline__ float fast_sigmoid(float x) {
    return __fdividef(1.f, 1.f + __expf(-x));
}
__device__ __forceinline__ float fast_tanh(float x) {
    return 1.f - __fdividef(2.f, __expf(2.f * x) + 1.f);
}

// D += A@B  (m16n8k16 fp16 in, fp32 accum, row.col)
__device__ __forceinline__ void mma16(float* d, const uint32_t* a, const uint32_t* b) {
    asm volatile("mma.sync.aligned.m16n8k16.row.col.f32.f16.f16.f32 "
        "{%0,%1,%2,%3}, {%4,%5,%6,%7}, {%8,%9}, {%0,%1,%2,%3};"
        : "+f"(d[0]), "+f"(d[1]), "+f"(d[2]), "+f"(d[3])
        : "r"(a[0]), "r"(a[1]), "r"(a[2]), "r"(a[3]), "r"(b[0]), "r"(b[1]));
}
// D += A@B  (m16n8k16 fp16 in, fp16 accum, row.col) — correction terms
__device__ __forceinline__ void mma16h(uint32_t* d, const uint32_t* a, const uint32_t* b) {
    asm volatile("mma.sync.aligned.m16n8k16.row.col.f16.f16.f16.f16 "
        "{%0,%1}, {%2,%3,%4,%5}, {%6,%7}, {%0,%1};"
        : "+r"(d[0]), "+r"(d[1])
        : "r"(a[0]), "r"(a[1]), "r"(a[2]), "r"(a[3]), "r"(b[0]), "r"(b[1]));
}

// ------------------------- epilogue activations -------------------------
template <int EPI>
__device__ __forceinline__ float act(float v) {
    if (EPI == 1) return fmaxf(v, 0.f);           // relu
    if (EPI == 2) return fast_tanh(v);            // tanh
    if (EPI == 3) return v > 0.f ? v : 0.01f * v; // leaky relu
    return v;
}

// ------------------------- weight prep: fp32 -> swizzled fp16 hi/lo blocks ----
__global__ void wprep_k(const float* __restrict__ src,
                        uint32_t* __restrict__ dh, uint32_t* __restrict__ dl,
                        int N, int trans)
{
    int z = blockIdx.z, tile = blockIdx.y, c = blockIdx.x;
    const float* Sp = src + (size_t)z * ((size_t)N * 256);
    size_t base = ((size_t)z * (N / 128) + tile) * 16384 + (size_t)c * 2048;
    for (int W = threadIdx.x; W < 2048; W += 256) {
        int nti = W >> 7, ks = (W >> 6) & 1, n8 = (W >> 3) & 7, w = W & 7;
        int wp = w ^ (ks << 1);
        int p = (wp >> 1) | ((wp & 1) << 2);
        int n = tile * 128 + nti * 8 + n8;
        int k0 = c * 32 + ks * 16 + 2 * p;
        float v0, v1;
        if (trans) { v0 = Sp[(size_t)k0 * N + n]; v1 = Sp[(size_t)(k0 + 1) * N + n]; }
        else       { v0 = Sp[(size_t)n * 256 + k0]; v1 = Sp[(size_t)n * 256 + k0 + 1]; }
        uint32_t h, l;
        split2(v0, v1, h, l);
        dh[base + W] = h;
        dl[base + W] = l;
    }
}

__global__ void bias4_k(const float* __restrict__ b0, const float* __restrict__ b1,
                        const float* __restrict__ b2, const float* __restrict__ b3)
{
    int t = blockIdx.x * 256 + threadIdx.x;   // 0..1023
    const float* src = (t < 256) ? b0 : (t < 512) ? b1 : (t < 768) ? b2 : b3;
    g_bias4[t] = src[t & 255];
}

// ------------------------- mma.sync fp16x3 GEMM (fp16-accum corrections) ----
template <int EPI, bool OUTH, bool SUBR>
__global__ void __launch_bounds__(256) mm_k(
    const float* __restrict__ A, long lda, long az,
    const uint32_t* __restrict__ Bh, const uint32_t* __restrict__ Bl, long bzw,
    const float* __restrict__ bias, long biz,
    void* __restrict__ Cv, long ldc, long cz,
    const float* __restrict__ R)
{
    extern __shared__ uint32_t smem[];
    const int t = threadIdx.x;
    const int m0 = blockIdx.y * 128;
    const int n0 = blockIdx.x * 128;
    const int z  = blockIdx.z;
    const float* Ap = A + (size_t)z * az + (size_t)m0 * lda;
    const uint32_t* Bhp = Bh + (size_t)z * bzw + (size_t)(n0 >> 7) * 16384;
    const uint32_t* Blp = Bl + (size_t)z * bzw + (size_t)(n0 >> 7) * 16384;
    const float* bp = bias + (size_t)z * biz + n0;

    const int lane = t & 31, w = t >> 5;
    const int wM = w >> 2, wN = w & 3;
    const int g = lane >> 2, cl = lane & 3;

    float acc[4][4][4];
    uint32_t cacc[4][4][2];
#pragma unroll
    for (int i = 0; i < 4; i++)
#pragma unroll
        for (int j = 0; j < 4; j++) {
#pragma unroll
            for (int k = 0; k < 4; k++) acc[i][j][k] = 0.f;
            cacc[i][j][0] = 0u; cacc[i][j][1] = 0u;
        }

    float4 va[4];
    uint4 rbh[2], rbl[2];

    auto ldstage = [&](int kb) {
#pragma unroll
        for (int i = 0; i < 4; i++) {
            int idx = t + i * 256, row = idx >> 3, f4 = idx & 7;
            va[i] = *(const float4*)(Ap + (size_t)row * lda + kb + f4 * 4);
            if (SUBR) {
                float4 rv = *(const float4*)(R + ((size_t)(m0 + row) << 8) + kb + f4 * 4);
                va[i].x = rv.x - va[i].x; va[i].y = rv.y - va[i].y;
                va[i].z = rv.z - va[i].z; va[i].w = rv.w - va[i].w;
            }
        }
        const uint32_t* bh = Bhp + (size_t)(kb >> 5) * 2048 + t * 8;
        const uint32_t* bl = Blp + (size_t)(kb >> 5) * 2048 + t * 8;
        rbh[0] = *(const uint4*)bh; rbh[1] = *(const uint4*)(bh + 4);
        rbl[0] = *(const uint4*)bl; rbl[1] = *(const uint4*)(bl + 4);
    };
    auto ststage = [&](int p) {
        uint32_t* A0 = smem + (p * 2 + 0) * 2048;
        uint32_t* A1 = smem + (p * 2 + 1) * 2048;
#pragma unroll
        for (int i = 0; i < 4; i++) {
            int idx = t + i * 256, row = idx >> 3, f4 = idx & 7;
            int ks = f4 >> 2, j = f4 & 3;
            int w0 = (2 * ((2 * j) & 3) + ((2 * j) >> 2)) ^ (ks << 1);
            int w1 = (2 * ((2 * j + 1) & 3) + ((2 * j + 1) >> 2)) ^ (ks << 1);
            uint32_t h0, l0, h1, l1;
            int mt = row >> 4, r = row & 15;
            int seg = (mt * 4 + ks * 2 + (r >> 3)) * 64 + (r & 7) * 8;
            split2(va[i].x, va[i].y, h0, l0);
            split2(va[i].z, va[i].w, h1, l1);
            A0[seg + w0] = h0; A1[seg + w0] = l0;
            A0[seg + w1] = h1; A1[seg + w1] = l1;
        }
        uint32_t* B0 = smem + 8192 + (p * 2 + 0) * 2048 + t * 8;
        uint32_t* B1 = smem + 8192 + (p * 2 + 1) * 2048 + t * 8;
        *(uint4*)B0 = rbh[0]; *(uint4*)(B0 + 4) = rbh[1];
        *(uint4*)B1 = rbl[0]; *(uint4*)(B1 + 4) = rbl[1];
    };
    auto compute = [&](int p) {
        const uint32_t* A0 = smem + (p * 2 + 0) * 2048;
        const uint32_t* A1 = smem + (p * 2 + 1) * 2048;
        const uint32_t* B0 = smem + 8192 + (p * 2 + 0) * 2048;
        const uint32_t* B1 = smem + 8192 + (p * 2 + 1) * 2048;
#pragma unroll
        for (int ks = 0; ks < 2; ks++) {
            const int cx = (cl * 2) ^ (ks << 1);
            uint32_t a0[4][4], a1[4][4], b0[4][2], b1[4][2];
#pragma unroll
            for (int mt = 0; mt < 4; mt++) {
                int mtg = wM * 4 + mt;
                int off = (mtg * 4 + ks * 2) * 64 + g * 8 + cx;
                uint2 lo0 = *(const uint2*)(A0 + off);
                uint2 hi0 = *(const uint2*)(A0 + off + 64);
                a0[mt][0] = lo0.x; a0[mt][2] = lo0.y;
                a0[mt][1] = hi0.x; a0[mt][3] = hi0.y;
                uint2 lo1 = *(const uint2*)(A1 + off);
                uint2 hi1 = *(const uint2*)(A1 + off + 64);
                a1[mt][0] = lo1.x; a1[mt][2] = lo1.y;
                a1[mt][1] = hi1.x; a1[mt][3] = hi1.y;
            }
#pragma unroll
            for (int nt = 0; nt < 4; nt++) {
                int ntg = wN * 4 + nt;
                int off = (ntg * 2 + ks) * 64 + g * 8 + cx;
                uint2 v0 = *(const uint2*)(B0 + off);
                b0[nt][0] = v0.x; b0[nt][1] = v0.y;
                uint2 v1 = *(const uint2*)(B1 + off);
                b1[nt][0] = v1.x; b1[nt][1] = v1.y;
            }
#pragma unroll
            for (int mt = 0; mt < 4; mt++)
#pragma unroll
                for (int nt = 0; nt < 4; nt++) {
                    mma16(acc[mt][nt], a0[mt], b0[nt]);     // hi*hi (fp32 accum)
                    mma16h(cacc[mt][nt], a0[mt], b1[nt]);   // hi*lo' (fp16 accum)
                    mma16h(cacc[mt][nt], a1[mt], b0[nt]);   // lo'*hi (fp16 accum)
                }
        }
    };

    ldstage(0);
    ststage(0);
    __syncthreads();
    int p = 0;
    for (int ch = 0; ch < 8; ch++) {
        if (ch < 7) ldstage((ch + 1) * 32);
        compute(p);
        if (ch < 7) {
            ststage(p ^ 1);
            __syncthreads();
            p ^= 1;
        }
    }

    const int wm = wM * 64, wn = wN * 32;
#pragma unroll
    for (int mt = 0; mt < 4; mt++) {
        int r0 = wm + mt * 16 + g;
#pragma unroll
        for (int nt = 0; nt < 4; nt++) {
            int col = wn + nt * 8 + (cl << 1);
            float2 b2 = *(const float2*)(bp + col);
            float2 fc0 = __half22float2(*reinterpret_cast<__half2*>(&cacc[mt][nt][0]));
            float2 fc1 = __half22float2(*reinterpret_cast<__half2*>(&cacc[mt][nt][1]));
            float2 o0, o1;
            o0.x = act<EPI>(fmaf(fc0.x, LO_INV, acc[mt][nt][0]) + b2.x);
            o0.y = act<EPI>(fmaf(fc0.y, LO_INV, acc[mt][nt][1]) + b2.y);
            o1.x = act<EPI>(fmaf(fc1.x, LO_INV, acc[mt][nt][2]) + b2.x);
            o1.y = act<EPI>(fmaf(fc1.y, LO_INV, acc[mt][nt][3]) + b2.y);
            if (OUTH) {
                __half* Ch = (__half*)Cv + (size_t)z * cz + (size_t)m0 * ldc + n0;
                *(__half2*)(Ch + (size_t)r0 * ldc + col)       = __floats2half2_rn(o0.x, o0.y);
                *(__half2*)(Ch + (size_t)(r0 + 8) * ldc + col) = __floats2half2_rn(o1.x, o1.y);
            } else {
                float* Cf = (float*)Cv + (size_t)z * cz + (size_t)m0 * ldc + n0;
                *(float2*)(Cf + (size_t)r0 * ldc + col) = o0;
                *(float2*)(Cf + (size_t)(r0 + 8) * ldc + col) = o1;
            }
        }
    }
}

// ------------------------- attention scores -------------------------
// QKVR layout: [row][0:256 Q | 256:512 K | 512:768 V | 768:1024 Vr]
__global__ void __launch_bounds__(256) scores_k(const float* __restrict__ QK)
{
    __shared__ float Ks[32][257];
    int b = blockIdx.x;
    int t = threadIdx.x;
    for (int idx = t; idx < S * H; idx += 256) {
        int k = idx >> 8, c = idx & 255;
        Ks[k][c] = QK[(size_t)(b * S + k) * 1024 + 256 + c];
    }
    __syncthreads();
    int lane = t & 31, w = t >> 5;
#pragma unroll
    for (int qi = 0; qi < 4; qi++) {
        int q = w + qi * 8;
        const float* qrow = QK + (size_t)(b * S + q) * 1024;
#pragma unroll
        for (int h = 0; h < NH; h++) {
            float accv = 0.f;
#pragma unroll 16
            for (int d = 0; d < HD; d++)
                accv = fmaf(__ldg(qrow + h * HD + d), Ks[lane][h * HD + d], accv);
            g_scores[(size_t)(h * NB + b) * (S * S) + q * S + lane] = accv * 0.125f;
        }
    }
}

// ------------------------- softmax over axis 0 (length 16384) per (q,k) -------------------------
__global__ void __launch_bounds__(256) smax_part_k()
{
    int chunk = blockIdx.x, q = blockIdx.y;
    int t = threadIdx.x, k = t & 31, g = t >> 5;
    float m = -1e30f, sv = 0.f;
    int base = chunk * 512 + g;
    for (int i = 0; i < 64; i++) {
        int bh = base + i * 8;
        float v = g_scores[(size_t)bh * 1024 + q * 32 + k];
        if (v > m) { sv = sv * __expf(m - v) + 1.f; m = v; }
        else       { sv += __expf(v - m); }
    }
    __shared__ float sm[8][32], ss[8][32];
    sm[g][k] = m; ss[g][k] = sv;
    __syncthreads();
    if (t < 32) {
        float M = sm[0][k];
#pragma unroll
        for (int j = 1; j < 8; j++) M = fmaxf(M, sm[j][k]);
        float Sv = 0.f;
#pragma unroll
        for (int j = 0; j < 8; j++) Sv += ss[j][k] * __expf(sm[j][k] - M);
        g_pmax[chunk * 1024 + q * 32 + k] = M;
        g_psum[chunk * 1024 + q * 32 + k] = Sv;
    }
}

__global__ void smax_final_k()
{
    int t = threadIdx.x;
    float M = -1e30f;
    for (int c = 0; c < 32; c++) M = fmaxf(M, g_pmax[c * 1024 + t]);
    float Sv = 0.f;
    for (int c = 0; c < 32; c++) Sv += g_psum[c * 1024 + t] * __expf(g_pmax[c * 1024 + t] - M);
    g_smax[t] = M;
    g_ssum[t] = Sv;
}

// ------------------------- weighted-V + Vr + relu + InstanceNorm (fused) -------------------------
__global__ void __launch_bounds__(256) attnout_k(
    const float* __restrict__ QKVR,
    const float* __restrict__ gamma, const float* __restrict__ beta,
    float* __restrict__ out)
{
    __shared__ float Vsm[32][256];
    __shared__ float wsm[4][32];
    __shared__ float s_stat[2];
    __shared__ float red[2][8];
    __shared__ float s_smax[1024], s_rs[1024];
    int b = blockIdx.x;
    int t = threadIdx.x;
    for (int idx = t; idx < 32 * 256; idx += 256) {
        int row = idx >> 8, c = idx & 255;
        Vsm[row][c] = QKVR[(size_t)(b * 32 + row) * 1024 + 512 + c];
    }
    for (int idx = t; idx < 1024; idx += 256) {
        s_smax[idx] = g_smax[idx];
        s_rs[idx]   = __fdividef(1.f, g_ssum[idx]);
    }
    float gam = gamma[t], bet = beta[t];
    int lane = t & 31, wid = t >> 5;
    int hh = t >> 6;
    __syncthreads();
    for (int q = 0; q < 32; q++) {
        if (t < 128) {
            int h = t >> 5, k = t & 31;
            float svv = g_scores[(size_t)(h * NB + b) * 1024 + q * 32 + k];
            wsm[h][k] = __expf(svv - s_smax[q * 32 + k]) * s_rs[q * 32 + k];
        }
        __syncthreads();
        float accv = 0.f;
#pragma unroll 8
        for (int k = 0; k < 32; k++)
            accv = fmaf(wsm[hh][k], Vsm[k][t], accv);
        float o = fmaxf(accv + QKVR[(size_t)(b * 32 + q) * 1024 + 768 + t], 0.f);
        float v1 = o, v2 = o * o;
#pragma unroll
        for (int off = 16; off; off >>= 1) {
            v1 += __shfl_down_sync(0xffffffffu, v1, off);
            v2 += __shfl_down_sync(0xffffffffu, v2, off);
        }
        if (lane == 0) { red[0][wid] = v1; red[1][wid] = v2; }
        __syncthreads();
        if (t == 0) {
            float s1 = 0.f, s2 = 0.f;
#pragma unroll
            for (int i = 0; i < 8; i++) { s1 += red[0][i]; s2 += red[1][i]; }
            float mu  = s1 * (1.f / 256.f);
            float var = s2 * (1.f / 256.f) - mu * mu;
            s_stat[0] = mu;
            s_stat[1] = rsqrtf(var + 1e-5f);
        }
        __syncthreads();
        out[(size_t)(b * 32 + q) * 256 + t] = gam * ((o - s_stat[0]) * s_stat[1]) + bet;
        __syncthreads();
    }
}

// ------------------------- GNN helpers -------------------------
__global__ void rowsum_k(const float* __restrict__ X, float* __restrict__ R)
{
    int idx = blockIdx.x * 256 + threadIdx.x;  // NB*H
    int b = idx >> 8, h = idx & 255;
    float accv = 0.f;
#pragma unroll
    for (int s = 0; s < 32; s++)
        accv += X[(size_t)((b << 5) + s) * 256 + h];
    R[idx] = accv;
    (void)h;
}

__global__ void gru_k(const float* __restrict__ xin, float* __restrict__ xout)
{
    size_t idx = (size_t)blockIdx.x * 256 + threadIdx.x;
    int row = (int)(idx >> 8), c = (int)(idx & 255);
    size_t base = (size_t)row * 768 + c;
    float ir = __half2float(g_gi[base]);
    float iz = __half2float(g_gi[base + 256]);
    float inn = __half2float(g_gi[base + 512]);
    float hr = __half2float(g_gh[base]);
    float hz = __half2float(g_gh[base + 256]);
    float hn = __half2float(g_gh[base + 512]);
    float r = fast_sigmoid(ir + hr);
    float z = fast_sigmoid(iz + hz);
    float n = fast_tanh(inn + r * hn);
    float x = xin[idx];
    xout[idx] = x + (1.f - z) * n + z * x;
}

// ------------------------- final credit head -------------------------
__global__ void __launch_bounds__(256) cred_k(
    const float* __restrict__ M1, const float* __restrict__ M2,
    float* __restrict__ out)
{
    int wid = threadIdx.x >> 5, lane = threadIdx.x & 31;
    int row = blockIdx.x * 8 + wid;
    const float* p1 = M1 + (size_t)row * 256;
    const float* p2 = M2 + (size_t)row * 256;
    float accv = 0.f;
#pragma unroll
    for (int j = 0; j < 8; j++)
        accv = fmaf(p1[lane + j * 32], p2[lane + j * 32], accv);
#pragma unroll
    for (int off = 16; off; off >>= 1)
        accv += __shfl_down_sync(0xffffffffu, accv, off);
    if (lane == 0) out[row] = fast_sigmoid(accv);
}

// ------------------------- host orchestration -------------------------
#define SMEM_MM 65536

extern "C" void kernel_launch(void* const* d_in, const int* in_sizes, int n_in,
                              void* d_out, int out_size)
{
    (void)in_sizes; (void)n_in; (void)out_size;
    const float* inputs  = (const float*)d_in[0];
    const float* embed_w = (const float*)d_in[1];
    const float* embed_b = (const float*)d_in[2];
    const float* wq  = (const float*)d_in[3];
    const float* bq  = (const float*)d_in[4];
    const float* wk  = (const float*)d_in[5];
    const float* bk  = (const float*)d_in[6];
    const float* wv  = (const float*)d_in[7];
    const float* bv  = (const float*)d_in[8];
    const float* wvr = (const float*)d_in[9];
    const float* bvr = (const float*)d_in[10];
    const float* gamma = (const float*)d_in[11];
    const float* beta  = (const float*)d_in[12];
    const float* mp_w1 = (const float*)d_in[13];
    const float* mp_b1 = (const float*)d_in[14];
    const float* mp_w3 = (const float*)d_in[15];
    const float* mp_b3 = (const float*)d_in[16];
    const float* gru_wih = (const float*)d_in[17];
    const float* gru_whh = (const float*)d_in[18];
    const float* gru_bih = (const float*)d_in[19];
    const float* gru_bhh = (const float*)d_in[20];
    const float* mlp1_w = (const float*)d_in[21];
    const float* mlp1_b = (const float*)d_in[22];
    const float* mlp2_w = (const float*)d_in[23];
    const float* mlp2_b = (const float*)d_in[24];

    float *feat, *qb, *kb, *qkvr, *attn, *xa, *xb, *rowsum, *bias4;
    uint32_t *wbh, *wbl;
    cudaGetSymbolAddress((void**)&feat,   g_feat);
    cudaGetSymbolAddress((void**)&qb,     g_q);
    cudaGetSymbolAddress((void**)&kb,     g_k);
    cudaGetSymbolAddress((void**)&qkvr,   g_qkvr);
    cudaGetSymbolAddress((void**)&attn,   g_attn);
    cudaGetSymbolAddress((void**)&xa,     g_xa);
    cudaGetSymbolAddress((void**)&xb,     g_xb);
    cudaGetSymbolAddress((void**)&rowsum, g_rowsum);
    cudaGetSymbolAddress((void**)&bias4,  g_bias4);
    cudaGetSymbolAddress((void**)&wbh,    g_wbh);
    cudaGetSymbolAddress((void**)&wbl,    g_wbl);
    __half *gi, *gh;
    cudaGetSymbolAddress((void**)&gi, g_gi);
    cudaGetSymbolAddress((void**)&gh, g_gh);

    cudaFuncSetAttribute(mm_k<0, false, false>, cudaFuncAttributeMaxDynamicSharedMemorySize, SMEM_MM);
    cudaFuncSetAttribute(mm_k<0, false, true >, cudaFuncAttributeMaxDynamicSharedMemorySize, SMEM_MM);
    cudaFuncSetAttribute(mm_k<0, true,  false>, cudaFuncAttributeMaxDynamicSharedMemorySize, SMEM_MM);
    cudaFuncSetAttribute(mm_k<1, false, false>, cudaFuncAttributeMaxDynamicSharedMemorySize, SMEM_MM);
    cudaFuncSetAttribute(mm_k<2, false, false>, cudaFuncAttributeMaxDynamicSharedMemorySize, SMEM_MM);
    cudaFuncSetAttribute(mm_k<3, false, false>, cudaFuncAttributeMaxDynamicSharedMemorySize, SMEM_MM);

    float* out_cred = (float*)d_out;
    float* out_fs   = (float*)d_out + BS;   // fs written in place

    // ---- one-time-per-replay weight prep (fp32 -> swizzled fp16 hi/lo) ----
    wprep_k<<<dim3(8, 2, 1),  256>>>(embed_w, wbh + W7_OFF + 0 * 32768, wbl + W7_OFF + 0 * 32768, 256, 1);
    wprep_k<<<dim3(8, 2, 1),  256>>>(wq,      wbh + W7_OFF + 1 * 32768, wbl + W7_OFF + 1 * 32768, 256, 1);
    wprep_k<<<dim3(8, 2, 1),  256>>>(wk,      wbh + W7_OFF + 2 * 32768, wbl + W7_OFF + 2 * 32768, 256, 1);
    wprep_k<<<dim3(8, 2, 1),  256>>>(wv,      wbh + W7_OFF + 3 * 32768, wbl + W7_OFF + 3 * 32768, 256, 1);
    wprep_k<<<dim3(8, 2, 1),  256>>>(wvr,     wbh + W7_OFF + 4 * 32768, wbl + W7_OFF + 4 * 32768, 256, 1);
    wprep_k<<<dim3(8, 2, 1),  256>>>(mlp1_w,  wbh + W7_OFF + 5 * 32768, wbl + W7_OFF + 5 * 32768, 256, 1);
    wprep_k<<<dim3(8, 2, 1),  256>>>(mlp2_w,  wbh + W7_OFF + 6 * 32768, wbl + W7_OFF + 6 * 32768, 256, 1);
    wprep_k<<<dim3(8, 2, 32), 256>>>(mp_w1,   wbh + W1_OFF,  wbl + W1_OFF,  256, 1);
    wprep_k<<<dim3(8, 2, 32), 256>>>(mp_w3,   wbh + W3_OFF,  wbl + W3_OFF,  256, 1);
    wprep_k<<<dim3(8, 6, 1),  256>>>(gru_wih, wbh + WIH_OFF, wbl + WIH_OFF, 768, 0);
    wprep_k<<<dim3(8, 6, 1),  256>>>(gru_whh, wbh + WHH_OFF, wbl + WHH_OFF, 768, 0);
    bias4_k<<<4, 256>>>(bq, bk, bv, bvr);

    dim3 g2(2, 1024);
    // feat = tanh(inputs @ embed_w + b)
    mm_k<2, false, false><<<g2, 256, SMEM_MM>>>(inputs, H, 0, wbh + W7_OFF, wbl + W7_OFF, 0, embed_b, 0, feat, H, 0, nullptr);
    // [Q|K|V|Vr] = relu(feat @ [wq|wk|wv|wvr] + [b4]) in ONE launch (weights contiguous)
    mm_k<1, false, false><<<dim3(8, 1024), 256, SMEM_MM>>>(feat, H, 0,
        wbh + W7_OFF + 32768, wbl + W7_OFF + 32768, 0, bias4, 0, qkvr, 1024, 0, nullptr);
    // attention
    scores_k<<<NB, 256>>>(qkvr);
    smax_part_k<<<dim3(32, 32), 256>>>();
    smax_final_k<<<1, 1024>>>();
    attnout_k<<<NB, 256>>>(qkvr, gamma, beta, attn);

    // GNN x4 (first output = fs, written directly to d_out region)
    const float* xin_seq[4]  = { attn,   out_fs, xa, xb };
    float*       xout_seq[4] = { out_fs, xa,     xb, xa };
    for (int it = 0; it < 4; it++) {
        const float* x_in = xin_seq[it];
        float* x_out = xout_seq[it];
        dim3 gs(2, 32, 32);  // n-tiles, m-tiles(4096/128), sender
        mm_k<0, false, false><<<gs, 256, SMEM_MM>>>(x_in, S * H, H, wbh + W1_OFF, wbl + W1_OFF, 32768, mp_b1, H, qb, S * H, H, nullptr);
        rowsum_k<<<(NB * H) / 256, 256>>>(qb, rowsum);
        mm_k<0, false, true ><<<gs, 256, SMEM_MM>>>(qb, S * H, H, wbh + W3_OFF, wbl + W3_OFF, 32768, mp_b3, H, kb, S * H, H, rowsum);
        mm_k<0, true,  false><<<dim3(6, 1024), 256, SMEM_MM>>>(kb,   H, 0, wbh + WIH_OFF, wbl + WIH_OFF, 0, gru_bih, 0, gi, 768, 0, nullptr);
        mm_k<0, true,  false><<<dim3(6, 1024), 256, SMEM_MM>>>(x_in, H, 0, wbh + WHH_OFF, wbl + WHH_OFF, 0, gru_bhh, 0, gh, 768, 0, nullptr);
        gru_k<<<(BS * H) / 256, 256>>>(x_in, x_out);
    }

    // head: m1 = tanh(fs3@mlp1), m2 = leaky(fs3@mlp2), cred = sigmoid(sum(m1*m2))
    mm_k<2, false, false><<<g2, 256, SMEM_MM>>>(xa, H, 0, wbh + W7_OFF + 5 * 32768, wbl + W7_OFF + 5 * 32768, 0, mlp1_b, 0, qb, H, 0, nullptr);
    mm_k<3, false, false><<<g2, 256, SMEM_MM>>>(xa, H, 0, wbh + W7_OFF + 6 * 32768, wbl + W7_OFF + 6 * 32768, 0, mlp2_b, 0, kb, H, 0, nullptr);
    cred_k<<<BS / 8, 256>>>(qb, kb, out_cred);
}